// round 1
// baseline (speedup 1.0000x reference)
#include <cuda_runtime.h>
#include <cstdint>
#include <cstddef>

// Problem constants
#define B_  2
#define S_  2048
#define D_  512
#define H_  8
#define HD_ 64
#define FF_ 2048
#define L_  2
#define EPS_ 1e-5f
#define NEG_ (-1000000000.0f)

// ---------------- scratch (static __device__ globals; no allocs) -------------
__device__ int   g_len[B_];
__device__ float g_bufX[B_ * S_ * D_];                       //  8 MB
__device__ float g_bufQKV[B_ * S_ * 3 * D_];                 // 24 MB
__device__ float g_bufP[(size_t)B_ * H_ * S_ * S_];          // 256 MB
__device__ float g_bufAttn[B_ * S_ * D_];                    //  8 MB
__device__ float g_bufY[B_ * S_ * D_];                       //  8 MB
__device__ float g_bufH[B_ * S_ * FF_];                      // 32 MB

// ---------------- mask prep: infer per-batch valid length --------------------
// The padded mask is a monotone prefix (arange < length). Its device dtype may
// be uint8 (numpy bool) or int32. Detect which by checking the prefix property
// under the byte interpretation; fall back to int32.
__global__ void prep_mask(const unsigned char* __restrict__ m8) {
    __shared__ int s_cnt, s_bad;
    const int* m32 = (const int*)m8;
    for (int b = 0; b < B_; b++) {
        if (threadIdx.x == 0) { s_cnt = 0; s_bad = 0; }
        __syncthreads();
        int local = 0;
        for (int j = threadIdx.x; j < S_; j += blockDim.x)
            local += (m8[b * S_ + j] != 0) ? 1 : 0;
        atomicAdd(&s_cnt, local);
        __syncthreads();
        int c = s_cnt;
        int bad = 0;
        for (int j = threadIdx.x; j < S_; j += blockDim.x) {
            int v = (m8[b * S_ + j] != 0) ? 1 : 0;
            if (v != ((j < c) ? 1 : 0)) bad = 1;
        }
        if (bad) atomicOr(&s_bad, 1);
        __syncthreads();
        if (s_bad != 0 || c < S_ / 2) {
            if (threadIdx.x == 0) s_cnt = 0;
            __syncthreads();
            local = 0;
            for (int j = threadIdx.x; j < S_; j += blockDim.x)
                local += (m32[b * S_ + j] != 0) ? 1 : 0;
            atomicAdd(&s_cnt, local);
            __syncthreads();
            c = s_cnt;
        }
        if (threadIdx.x == 0) g_len[b] = c;
        __syncthreads();
    }
}

// ---------------- generic batched SGEMM --------------------------------------
// C[M,N] = A[M,K] * op(B) (+ epilogue).  Row-major, leading dims lda/ldb/ldc,
// per-z batch strides sA/sB/sC.  TRANSB: C[i,j] = sum_k A[i,k]*B[j,k].
// EPI: 0 = none, 1 = +bias, 2 = relu(+bias), 3 = QK: *alpha then mask cols>=len
template<int EPI, bool TRANSB>
__global__ void sgemm(int M, int N, int K,
                      const float* __restrict__ A, int lda, size_t sA,
                      const float* __restrict__ B, int ldb, size_t sB,
                      float* __restrict__ C, int ldc, size_t sC,
                      const float* __restrict__ bias, float alpha)
{
    const int z = blockIdx.z;
    A += (size_t)z * sA;
    B += (size_t)z * sB;
    C += (size_t)z * sC;

    __shared__ float As[16][65];
    __shared__ float Bs[16][65];

    const int bm = blockIdx.y * 64;
    const int bn = blockIdx.x * 64;
    const int tid = threadIdx.x;          // 256 threads
    const int tx = tid & 15;              // 0..15 (cols)
    const int ty = tid >> 4;              // 0..15 (rows)

    float acc[4][4] = {};

    for (int k0 = 0; k0 < K; k0 += 16) {
        // Load A tile (64 x 16), stored transposed: As[k][m]
        {
            int m = tid >> 4, k = tid & 15;
            #pragma unroll
            for (int i = 0; i < 4; i++)
                As[k][m + 16 * i] = A[(size_t)(bm + m + 16 * i) * lda + (k0 + k)];
        }
        if (TRANSB) {
            int n = tid >> 4, k = tid & 15;
            #pragma unroll
            for (int i = 0; i < 4; i++)
                Bs[k][n + 16 * i] = B[(size_t)(bn + n + 16 * i) * ldb + (k0 + k)];
        } else {
            int n = tid & 63, k = tid >> 6;
            #pragma unroll
            for (int i = 0; i < 4; i++)
                Bs[k + 4 * i][n] = B[(size_t)(k0 + k + 4 * i) * ldb + (bn + n)];
        }
        __syncthreads();

        #pragma unroll
        for (int kk = 0; kk < 16; kk++) {
            float a[4], b[4];
            #pragma unroll
            for (int i = 0; i < 4; i++) a[i] = As[kk][ty * 4 + i];
            #pragma unroll
            for (int j = 0; j < 4; j++) b[j] = Bs[kk][tx * 4 + j];
            #pragma unroll
            for (int i = 0; i < 4; i++)
                #pragma unroll
                for (int j = 0; j < 4; j++)
                    acc[i][j] = fmaf(a[i], b[j], acc[i][j]);
        }
        __syncthreads();
    }

    const int row0 = bm + ty * 4;
    const int col0 = bn + tx * 4;

    if (EPI == 3) {
        const int len = g_len[z / H_];
        #pragma unroll
        for (int i = 0; i < 4; i++) {
            #pragma unroll
            for (int j = 0; j < 4; j++) {
                int col = col0 + j;
                float v = acc[i][j] * alpha;
                C[(size_t)(row0 + i) * ldc + col] = (col < len) ? v : NEG_;
            }
        }
    } else {
        #pragma unroll
        for (int i = 0; i < 4; i++) {
            #pragma unroll
            for (int j = 0; j < 4; j++) {
                float v = acc[i][j];
                if (EPI >= 1) v += bias[col0 + j];
                if (EPI == 2) v = fmaxf(v, 0.0f);
                C[(size_t)(row0 + i) * ldc + (col0 + j)] = v;
            }
        }
    }
    (void)alpha; (void)bias;
}

// ---------------- reductions -------------------------------------------------
__device__ __forceinline__ float warpSum(float v) {
    #pragma unroll
    for (int o = 16; o > 0; o >>= 1) v += __shfl_xor_sync(0xffffffffu, v, o);
    return v;
}
__device__ __forceinline__ float warpMax(float v) {
    #pragma unroll
    for (int o = 16; o > 0; o >>= 1) v = fmaxf(v, __shfl_xor_sync(0xffffffffu, v, o));
    return v;
}

// ---------------- softmax over rows of P (with row-mask zeroing) -------------
__global__ void softmax_rows(float* __restrict__ P) {
    const size_t r = blockIdx.x;                  // row in [0, B*H*S)
    const int bh = (int)(r / S_);
    const int q  = (int)(r % S_);
    const int b  = bh / H_;
    float* row = P + r * (size_t)S_;
    const int t = threadIdx.x;                    // 256 threads

    if (q >= g_len[b]) {                          // masked query row -> zeros
        #pragma unroll
        for (int i = 0; i < 8; i++) row[t + 256 * i] = 0.0f;
        return;
    }

    __shared__ float sm1[8], sm2[8];
    const int lane = t & 31, wid = t >> 5;

    float v[8];
    float mx = -3.4e38f;
    #pragma unroll
    for (int i = 0; i < 8; i++) { v[i] = row[t + 256 * i]; mx = fmaxf(mx, v[i]); }
    float w = warpMax(mx);
    if (lane == 0) sm1[wid] = w;
    __syncthreads();
    float m = sm1[0];
    #pragma unroll
    for (int i = 1; i < 8; i++) m = fmaxf(m, sm1[i]);

    float s = 0.0f;
    #pragma unroll
    for (int i = 0; i < 8; i++) { float e = __expf(v[i] - m); v[i] = e; s += e; }
    w = warpSum(s);
    if (lane == 0) sm2[wid] = w;
    __syncthreads();
    float tot = 0.0f;
    #pragma unroll
    for (int i = 0; i < 8; i++) tot += sm2[i];
    float inv = 1.0f / tot;
    #pragma unroll
    for (int i = 0; i < 8; i++) row[t + 256 * i] = v[i] * inv;
}

// ---------------- fused residual-add + LayerNorm -----------------------------
__global__ void add_ln(const float* __restrict__ Y, const float* __restrict__ R,
                       const float* __restrict__ g, const float* __restrict__ be,
                       float* __restrict__ out)
{
    const int r = blockIdx.x;                     // 0..B*S-1
    const float* y = Y + (size_t)r * D_;
    const float* x = R + (size_t)r * D_;
    float* o = out + (size_t)r * D_;
    const int t = threadIdx.x;                    // 128 threads, 4 elems each
    const int lane = t & 31, wid = t >> 5;
    __shared__ float sm1[4], sm2[4];

    float v[4];
    float s = 0.0f;
    #pragma unroll
    for (int i = 0; i < 4; i++) { v[i] = y[t + 128 * i] + x[t + 128 * i]; s += v[i]; }
    float w = warpSum(s);
    if (lane == 0) sm1[wid] = w;
    __syncthreads();
    float mean = (sm1[0] + sm1[1] + sm1[2] + sm1[3]) * (1.0f / D_);

    float vs = 0.0f;
    #pragma unroll
    for (int i = 0; i < 4; i++) { float d = v[i] - mean; vs += d * d; }
    w = warpSum(vs);
    if (lane == 0) sm2[wid] = w;
    __syncthreads();
    float rstd = rsqrtf((sm2[0] + sm2[1] + sm2[2] + sm2[3]) * (1.0f / D_) + EPS_);

    #pragma unroll
    for (int i = 0; i < 4; i++)
        o[t + 128 * i] = g[t + 128 * i] * (v[i] - mean) * rstd + be[t + 128 * i];
}

// ---------------- launch -----------------------------------------------------
extern "C" void kernel_launch(void* const* d_in, const int* in_sizes, int n_in,
                              void* d_out, int out_size)
{
    const float* x    = (const float*)d_in[0];
    const unsigned char* mask = (const unsigned char*)d_in[1];
    const float* Wqkv = (const float*)d_in[2];
    const float* Wo   = (const float*)d_in[3];
    const float* bo   = (const float*)d_in[4];
    const float* g1   = (const float*)d_in[5];
    const float* be1  = (const float*)d_in[6];
    const float* W1   = (const float*)d_in[7];
    const float* bf1  = (const float*)d_in[8];
    const float* W2   = (const float*)d_in[9];
    const float* bf2  = (const float*)d_in[10];
    const float* g2   = (const float*)d_in[11];
    const float* be2  = (const float*)d_in[12];
    float* out = (float*)d_out;

    float *bufX, *bufQKV, *bufP, *bufAttn, *bufY, *bufH;
    cudaGetSymbolAddress((void**)&bufX,    g_bufX);
    cudaGetSymbolAddress((void**)&bufQKV,  g_bufQKV);
    cudaGetSymbolAddress((void**)&bufP,    g_bufP);
    cudaGetSymbolAddress((void**)&bufAttn, g_bufAttn);
    cudaGetSymbolAddress((void**)&bufY,    g_bufY);
    cudaGetSymbolAddress((void**)&bufH,    g_bufH);

    prep_mask<<<1, 256>>>(mask);

    const int M = B_ * S_;        // 4096 token rows
    const size_t sQKV = (size_t)S_ * 3 * HD_;   // per-(b,h) stride into QKV
    const size_t sP   = (size_t)S_ * S_;
    const size_t sO   = (size_t)S_ * HD_;

    for (int l = 0; l < L_; l++) {
        const float* cur = (l == 0) ? x : bufX;

        // QKV projection: [4096,512] @ [512,1536]
        sgemm<0, false><<<dim3(3 * D_ / 64, M / 64, 1), 256>>>(
            M, 3 * D_, D_,
            cur, D_, 0,
            Wqkv + (size_t)l * D_ * 3 * D_, 3 * D_, 0,
            bufQKV, 3 * D_, 0, nullptr, 1.0f);

        // Logits: per (b,h): Q @ K^T / 8, masked cols -> NEG
        sgemm<3, true><<<dim3(S_ / 64, S_ / 64, B_ * H_), 256>>>(
            S_, S_, HD_,
            bufQKV,        3 * HD_, sQKV,
            bufQKV + HD_,  3 * HD_, sQKV,
            bufP, S_, sP, nullptr, 0.125f);

        // Softmax (+zero masked query rows)
        softmax_rows<<<B_ * H_ * S_, 256>>>(bufP);

        // P @ V  -> attn output in the reference's raw [b,h,s,hd] layout
        sgemm<0, false><<<dim3(1, S_ / 64, B_ * H_), 256>>>(
            S_, HD_, S_,
            bufP, S_, sP,
            bufQKV + 2 * HD_, 3 * HD_, sQKV,
            bufAttn, HD_, sO, nullptr, 1.0f);

        // Output projection + bias (reads attn buffer reinterpreted as [4096,512])
        sgemm<1, false><<<dim3(D_ / 64, M / 64, 1), 256>>>(
            M, D_, D_,
            bufAttn, D_, 0,
            Wo + (size_t)l * D_ * D_, D_, 0,
            bufY, D_, 0, bo + (size_t)l * D_, 1.0f);

        // x = LN(attn_out + residual)
        add_ln<<<M, 128>>>(bufY, cur, g1 + (size_t)l * D_, be1 + (size_t)l * D_, bufX);

        // FFN1: relu(x @ W1 + bf1)
        sgemm<2, false><<<dim3(FF_ / 64, M / 64, 1), 256>>>(
            M, FF_, D_,
            bufX, D_, 0,
            W1 + (size_t)l * D_ * FF_, FF_, 0,
            bufH, FF_, 0, bf1 + (size_t)l * FF_, 1.0f);

        // FFN2: h @ W2 + bf2
        sgemm<1, false><<<dim3(D_ / 64, M / 64, 1), 256>>>(
            M, D_, FF_,
            bufH, FF_, 0,
            W2 + (size_t)l * FF_ * D_, D_, 0,
            bufY, D_, 0, bf2 + (size_t)l * D_, 1.0f);

        // x = LN(ffn_out + x); last layer writes the output buffer
        float* dst = (l == L_ - 1) ? out : bufX;
        add_ln<<<M, 128>>>(bufY, bufX, g2 + (size_t)l * D_, be2 + (size_t)l * D_, dst);
    }
    (void)in_sizes; (void)n_in; (void)out_size;
}

// round 2
// speedup vs baseline: 1.0008x; 1.0008x over previous
#include <cuda_runtime.h>
#include <cstdint>
#include <cstddef>

// Problem constants
#define B_  2
#define S_  2048
#define D_  512
#define H_  8
#define HD_ 64
#define FF_ 2048
#define L_  2
#define EPS_ 1e-5f
#define NEG_ (-1000000000.0f)

// ---------------- scratch (static __device__ globals; no allocs) -------------
__device__ int   g_len[B_];
__device__ float g_bufX[B_ * S_ * D_];                       //  8 MB
__device__ float g_bufQKV[B_ * S_ * 3 * D_];                 // 24 MB
__device__ float g_bufP[(size_t)B_ * H_ * S_ * S_];          // 256 MB
__device__ float g_bufAttn[B_ * S_ * D_];                    //  8 MB
__device__ float g_bufY[B_ * S_ * D_];                       //  8 MB
__device__ float g_bufH[B_ * S_ * FF_];                      // 32 MB

// ---------------- mask prep: infer per-batch valid length --------------------
// The padded mask is a monotone prefix (arange < length). Its device dtype may
// be uint8 (numpy bool) or int32. Detect which by checking the prefix property
// under the byte interpretation; fall back to int32.
__global__ void prep_mask(const unsigned char* __restrict__ m8) {
    __shared__ int s_cnt, s_bad;
    const int* m32 = (const int*)m8;
    for (int b = 0; b < B_; b++) {
        if (threadIdx.x == 0) { s_cnt = 0; s_bad = 0; }
        __syncthreads();
        int local = 0;
        for (int j = threadIdx.x; j < S_; j += blockDim.x)
            local += (m8[b * S_ + j] != 0) ? 1 : 0;
        atomicAdd(&s_cnt, local);
        __syncthreads();
        int c = s_cnt;
        int bad = 0;
        for (int j = threadIdx.x; j < S_; j += blockDim.x) {
            int v = (m8[b * S_ + j] != 0) ? 1 : 0;
            if (v != ((j < c) ? 1 : 0)) bad = 1;
        }
        if (bad) atomicOr(&s_bad, 1);
        __syncthreads();
        if (s_bad != 0 || c < S_ / 2) {
            if (threadIdx.x == 0) s_cnt = 0;
            __syncthreads();
            local = 0;
            for (int j = threadIdx.x; j < S_; j += blockDim.x)
                local += (m32[b * S_ + j] != 0) ? 1 : 0;
            atomicAdd(&s_cnt, local);
            __syncthreads();
            c = s_cnt;
        }
        if (threadIdx.x == 0) g_len[b] = c;
        __syncthreads();
    }
}

// ---------------- generic batched SGEMM --------------------------------------
// C[M,N] = A[M,K] * op(B) (+ epilogue).  Row-major, leading dims lda/ldb/ldc,
// per-z batch strides sA/sB/sC.  TRANSB: C[i,j] = sum_k A[i,k]*B[j,k].
// EPI: 0 = none, 1 = +bias, 2 = relu(+bias), 3 = QK: *alpha then mask cols>=len
template<int EPI, bool TRANSB>
__global__ void sgemm(int M, int N, int K,
                      const float* __restrict__ A, int lda, size_t sA,
                      const float* __restrict__ B, int ldb, size_t sB,
                      float* __restrict__ C, int ldc, size_t sC,
                      const float* __restrict__ bias, float alpha)
{
    const int z = blockIdx.z;
    A += (size_t)z * sA;
    B += (size_t)z * sB;
    C += (size_t)z * sC;

    __shared__ float As[16][65];
    __shared__ float Bs[16][65];

    const int bm = blockIdx.y * 64;
    const int bn = blockIdx.x * 64;
    const int tid = threadIdx.x;          // 256 threads
    const int tx = tid & 15;              // 0..15 (cols)
    const int ty = tid >> 4;              // 0..15 (rows)

    float acc[4][4] = {};

    for (int k0 = 0; k0 < K; k0 += 16) {
        // Load A tile (64 x 16), stored transposed: As[k][m]
        {
            int m = tid >> 4, k = tid & 15;
            #pragma unroll
            for (int i = 0; i < 4; i++)
                As[k][m + 16 * i] = A[(size_t)(bm + m + 16 * i) * lda + (k0 + k)];
        }
        if (TRANSB) {
            int n = tid >> 4, k = tid & 15;
            #pragma unroll
            for (int i = 0; i < 4; i++)
                Bs[k][n + 16 * i] = B[(size_t)(bn + n + 16 * i) * ldb + (k0 + k)];
        } else {
            int n = tid & 63, k = tid >> 6;
            #pragma unroll
            for (int i = 0; i < 4; i++)
                Bs[k + 4 * i][n] = B[(size_t)(k0 + k + 4 * i) * ldb + (bn + n)];
        }
        __syncthreads();

        #pragma unroll
        for (int kk = 0; kk < 16; kk++) {
            float a[4], b[4];
            #pragma unroll
            for (int i = 0; i < 4; i++) a[i] = As[kk][ty * 4 + i];
            #pragma unroll
            for (int j = 0; j < 4; j++) b[j] = Bs[kk][tx * 4 + j];
            #pragma unroll
            for (int i = 0; i < 4; i++)
                #pragma unroll
                for (int j = 0; j < 4; j++)
                    acc[i][j] = fmaf(a[i], b[j], acc[i][j]);
        }
        __syncthreads();
    }

    const int row0 = bm + ty * 4;
    const int col0 = bn + tx * 4;

    if (EPI == 3) {
        const int len = g_len[z / H_];
        #pragma unroll
        for (int i = 0; i < 4; i++) {
            #pragma unroll
            for (int j = 0; j < 4; j++) {
                int col = col0 + j;
                float v = acc[i][j] * alpha;
                C[(size_t)(row0 + i) * ldc + col] = (col < len) ? v : NEG_;
            }
        }
    } else {
        #pragma unroll
        for (int i = 0; i < 4; i++) {
            #pragma unroll
            for (int j = 0; j < 4; j++) {
                float v = acc[i][j];
                if (EPI >= 1) v += bias[col0 + j];
                if (EPI == 2) v = fmaxf(v, 0.0f);
                C[(size_t)(row0 + i) * ldc + (col0 + j)] = v;
            }
        }
    }
    (void)alpha; (void)bias;
}

// ---------------- reductions -------------------------------------------------
__device__ __forceinline__ float warpSum(float v) {
    #pragma unroll
    for (int o = 16; o > 0; o >>= 1) v += __shfl_xor_sync(0xffffffffu, v, o);
    return v;
}
__device__ __forceinline__ float warpMax(float v) {
    #pragma unroll
    for (int o = 16; o > 0; o >>= 1) v = fmaxf(v, __shfl_xor_sync(0xffffffffu, v, o));
    return v;
}

// ---------------- softmax over rows of P (with row-mask zeroing) -------------
__global__ void softmax_rows(float* __restrict__ P) {
    const size_t r = blockIdx.x;                  // row in [0, B*H*S)
    const int bh = (int)(r / S_);
    const int q  = (int)(r % S_);
    const int b  = bh / H_;
    float* row = P + r * (size_t)S_;
    const int t = threadIdx.x;                    // 256 threads

    if (q >= g_len[b]) {                          // masked query row -> zeros
        #pragma unroll
        for (int i = 0; i < 8; i++) row[t + 256 * i] = 0.0f;
        return;
    }

    __shared__ float sm1[8], sm2[8];
    const int lane = t & 31, wid = t >> 5;

    float v[8];
    float mx = -3.4e38f;
    #pragma unroll
    for (int i = 0; i < 8; i++) { v[i] = row[t + 256 * i]; mx = fmaxf(mx, v[i]); }
    float w = warpMax(mx);
    if (lane == 0) sm1[wid] = w;
    __syncthreads();
    float m = sm1[0];
    #pragma unroll
    for (int i = 1; i < 8; i++) m = fmaxf(m, sm1[i]);

    float s = 0.0f;
    #pragma unroll
    for (int i = 0; i < 8; i++) { float e = __expf(v[i] - m); v[i] = e; s += e; }
    w = warpSum(s);
    if (lane == 0) sm2[wid] = w;
    __syncthreads();
    float tot = 0.0f;
    #pragma unroll
    for (int i = 0; i < 8; i++) tot += sm2[i];
    float inv = 1.0f / tot;
    #pragma unroll
    for (int i = 0; i < 8; i++) row[t + 256 * i] = v[i] * inv;
}

// ---------------- fused residual-add + LayerNorm -----------------------------
__global__ void add_ln(const float* __restrict__ Y, const float* __restrict__ R,
                       const float* __restrict__ g, const float* __restrict__ be,
                       float* __restrict__ out)
{
    const int r = blockIdx.x;                     // 0..B*S-1
    const float* y = Y + (size_t)r * D_;
    const float* x = R + (size_t)r * D_;
    float* o = out + (size_t)r * D_;
    const int t = threadIdx.x;                    // 128 threads, 4 elems each
    const int lane = t & 31, wid = t >> 5;
    __shared__ float sm1[4], sm2[4];

    float v[4];
    float s = 0.0f;
    #pragma unroll
    for (int i = 0; i < 4; i++) { v[i] = y[t + 128 * i] + x[t + 128 * i]; s += v[i]; }
    float w = warpSum(s);
    if (lane == 0) sm1[wid] = w;
    __syncthreads();
    float mean = (sm1[0] + sm1[1] + sm1[2] + sm1[3]) * (1.0f / D_);

    float vs = 0.0f;
    #pragma unroll
    for (int i = 0; i < 4; i++) { float d = v[i] - mean; vs += d * d; }
    w = warpSum(vs);
    if (lane == 0) sm2[wid] = w;
    __syncthreads();
    float rstd = rsqrtf((sm2[0] + sm2[1] + sm2[2] + sm2[3]) * (1.0f / D_) + EPS_);

    #pragma unroll
    for (int i = 0; i < 4; i++)
        o[t + 128 * i] = g[t + 128 * i] * (v[i] - mean) * rstd + be[t + 128 * i];
}

// ---------------- launch -----------------------------------------------------
extern "C" void kernel_launch(void* const* d_in, const int* in_sizes, int n_in,
                              void* d_out, int out_size)
{
    const float* x    = (const float*)d_in[0];
    const unsigned char* mask = (const unsigned char*)d_in[1];
    const float* Wqkv = (const float*)d_in[2];
    const float* Wo   = (const float*)d_in[3];
    const float* bo   = (const float*)d_in[4];
    const float* g1   = (const float*)d_in[5];
    const float* be1  = (const float*)d_in[6];
    const float* W1   = (const float*)d_in[7];
    const float* bf1  = (const float*)d_in[8];
    const float* W2   = (const float*)d_in[9];
    const float* bf2  = (const float*)d_in[10];
    const float* g2   = (const float*)d_in[11];
    const float* be2  = (const float*)d_in[12];
    float* out = (float*)d_out;

    float *bufX, *bufQKV, *bufP, *bufAttn, *bufY, *bufH;
    cudaGetSymbolAddress((void**)&bufX,    g_bufX);
    cudaGetSymbolAddress((void**)&bufQKV,  g_bufQKV);
    cudaGetSymbolAddress((void**)&bufP,    g_bufP);
    cudaGetSymbolAddress((void**)&bufAttn, g_bufAttn);
    cudaGetSymbolAddress((void**)&bufY,    g_bufY);
    cudaGetSymbolAddress((void**)&bufH,    g_bufH);

    prep_mask<<<1, 256>>>(mask);

    const int M = B_ * S_;        // 4096 token rows
    const size_t sQKV = (size_t)S_ * 3 * HD_;   // per-(b,h) stride into QKV
    const size_t sP   = (size_t)S_ * S_;
    const size_t sO   = (size_t)S_ * HD_;

    for (int l = 0; l < L_; l++) {
        const float* cur = (l == 0) ? x : bufX;

        // QKV projection: [4096,512] @ [512,1536]
        sgemm<0, false><<<dim3(3 * D_ / 64, M / 64, 1), 256>>>(
            M, 3 * D_, D_,
            cur, D_, 0,
            Wqkv + (size_t)l * D_ * 3 * D_, 3 * D_, 0,
            bufQKV, 3 * D_, 0, nullptr, 1.0f);

        // Logits: per (b,h): Q @ K^T / 8, masked cols -> NEG
        sgemm<3, true><<<dim3(S_ / 64, S_ / 64, B_ * H_), 256>>>(
            S_, S_, HD_,
            bufQKV,        3 * HD_, sQKV,
            bufQKV + HD_,  3 * HD_, sQKV,
            bufP, S_, sP, nullptr, 0.125f);

        // Softmax (+zero masked query rows)
        softmax_rows<<<B_ * H_ * S_, 256>>>(bufP);

        // P @ V  -> attn output in the reference's raw [b,h,s,hd] layout
        sgemm<0, false><<<dim3(1, S_ / 64, B_ * H_), 256>>>(
            S_, HD_, S_,
            bufP, S_, sP,
            bufQKV + 2 * HD_, 3 * HD_, sQKV,
            bufAttn, HD_, sO, nullptr, 1.0f);

        // Output projection + bias (reads attn buffer reinterpreted as [4096,512])
        sgemm<1, false><<<dim3(D_ / 64, M / 64, 1), 256>>>(
            M, D_, D_,
            bufAttn, D_, 0,
            Wo + (size_t)l * D_ * D_, D_, 0,
            bufY, D_, 0, bo + (size_t)l * D_, 1.0f);

        // x = LN(attn_out + residual)
        add_ln<<<M, 128>>>(bufY, cur, g1 + (size_t)l * D_, be1 + (size_t)l * D_, bufX);

        // FFN1: relu(x @ W1 + bf1)
        sgemm<2, false><<<dim3(FF_ / 64, M / 64, 1), 256>>>(
            M, FF_, D_,
            bufX, D_, 0,
            W1 + (size_t)l * D_ * FF_, FF_, 0,
            bufH, FF_, 0, bf1 + (size_t)l * FF_, 1.0f);

        // FFN2: h @ W2 + bf2
        sgemm<1, false><<<dim3(D_ / 64, M / 64, 1), 256>>>(
            M, D_, FF_,
            bufH, FF_, 0,
            W2 + (size_t)l * FF_ * D_, D_, 0,
            bufY, D_, 0, bf2 + (size_t)l * D_, 1.0f);

        // x = LN(ffn_out + x); last layer writes the output buffer
        float* dst = (l == L_ - 1) ? out : bufX;
        add_ln<<<M, 128>>>(bufY, bufX, g2 + (size_t)l * D_, be2 + (size_t)l * D_, dst);
    }
    (void)in_sizes; (void)n_in; (void)out_size;
}

// round 4
// speedup vs baseline: 2.3382x; 2.3364x over previous
#include <cuda_runtime.h>
#include <cuda_bf16.h>
#include <cstdint>
#include <cstddef>

#define B_  2
#define S_  2048
#define D_  512
#define H_  8
#define HD_ 64
#define FF_ 2048
#define L_  2
#define EPS_ 1e-5f

typedef __nv_bfloat16 bf16;

// ===================== PTX helpers (all non-'a' gated) ======================
__device__ __forceinline__ uint32_t smem_u32(const void* p) {
    uint32_t a;
    asm("{ .reg .u64 t; cvta.to.shared.u64 t, %1; cvt.u32.u64 %0, t; }" : "=r"(a) : "l"(p));
    return a;
}
__device__ __forceinline__ void cp16(uint32_t dst, const void* src) {
    asm volatile("cp.async.cg.shared.global [%0], [%1], 16;" :: "r"(dst), "l"(src));
}
#define CPC  asm volatile("cp.async.commit_group;" ::: "memory")
#define CPW1 asm volatile("cp.async.wait_group 1;" ::: "memory")
#define CPW0 asm volatile("cp.async.wait_group 0;" ::: "memory")
#define LDSM4(r0, r1, r2, r3, a) \
    asm volatile("ldmatrix.sync.aligned.m8n8.x4.shared.b16 {%0,%1,%2,%3}, [%4];" \
                 : "=r"(r0), "=r"(r1), "=r"(r2), "=r"(r3) : "r"(a))

__device__ __forceinline__ void mma16816(float* c, const uint32_t* a, const uint32_t* b) {
    asm volatile("mma.sync.aligned.m16n8k16.row.col.f32.bf16.bf16.f32 "
                 "{%0,%1,%2,%3}, {%4,%5,%6,%7}, {%8,%9}, {%0,%1,%2,%3};"
                 : "+f"(c[0]), "+f"(c[1]), "+f"(c[2]), "+f"(c[3])
                 : "r"(a[0]), "r"(a[1]), "r"(a[2]), "r"(a[3]), "r"(b[0]), "r"(b[1]));
}

// ===================== device scratch =======================================
__device__ int  g_len[B_];
__device__ bf16 g_xh[B_*S_*D_],  g_xl[B_*S_*D_];
__device__ bf16 g_qh[B_*S_*3*D_], g_ql[B_*S_*3*D_];
__device__ bf16 g_vth[B_*H_*HD_*S_], g_vtl[B_*H_*HD_*S_];
__device__ float g_Pf[(size_t)B_*H_*S_*S_];
__device__ bf16 g_ph[(size_t)B_*H_*S_*S_], g_pl[(size_t)B_*H_*S_*S_];
__device__ bf16 g_ah[B_*S_*D_], g_al[B_*S_*D_];
__device__ float g_Yf[B_*S_*D_], g_r1[B_*S_*D_], g_r2[B_*S_*D_];
__device__ bf16 g_hh[B_*S_*FF_], g_hl[B_*S_*FF_];
__device__ bf16 g_wqT[2][L_*3*D_*D_];
__device__ bf16 g_woT[2][L_*D_*D_];
__device__ bf16 g_w1T[2][L_*FF_*D_];
__device__ bf16 g_w2T[2][L_*D_*FF_];

__device__ __forceinline__ void split_store(float v, bf16* H, bf16* L, size_t i) {
    bf16 h = __float2bfloat16(v);
    H[i] = h;
    L[i] = __float2bfloat16(v - __bfloat162float(h));
}

// ===================== mask prep (validated R1) =============================
__global__ void prep_mask(const unsigned char* __restrict__ m8) {
    __shared__ int s_cnt, s_bad;
    const int* m32 = (const int*)m8;
    for (int b = 0; b < B_; b++) {
        if (threadIdx.x == 0) { s_cnt = 0; s_bad = 0; }
        __syncthreads();
        int local = 0;
        for (int j = threadIdx.x; j < S_; j += blockDim.x)
            local += (m8[b * S_ + j] != 0) ? 1 : 0;
        atomicAdd(&s_cnt, local);
        __syncthreads();
        int c = s_cnt, bad = 0;
        for (int j = threadIdx.x; j < S_; j += blockDim.x) {
            int v = (m8[b * S_ + j] != 0) ? 1 : 0;
            if (v != ((j < c) ? 1 : 0)) bad = 1;
        }
        if (bad) atomicOr(&s_bad, 1);
        __syncthreads();
        if (s_bad != 0 || c < S_ / 2) {
            if (threadIdx.x == 0) s_cnt = 0;
            __syncthreads();
            local = 0;
            for (int j = threadIdx.x; j < S_; j += blockDim.x)
                local += (m32[b * S_ + j] != 0) ? 1 : 0;
            atomicAdd(&s_cnt, local);
            __syncthreads();
            c = s_cnt;
        }
        if (threadIdx.x == 0) g_len[b] = c;
        __syncthreads();
    }
}

// ===================== conversions ==========================================
__global__ void convert_split(const float* __restrict__ in, bf16* __restrict__ hi,
                              bf16* __restrict__ lo, int n) {
    int i = blockIdx.x * blockDim.x + threadIdx.x;
    if (i < n) split_store(in[i], hi, lo, i);
}

// W[K,N] fp32 -> T[N,K] split bf16
__global__ void transpose_split(const float* __restrict__ W, bf16* __restrict__ Th,
                                bf16* __restrict__ Tl, int K, int N) {
    __shared__ float t[32][33];
    int n0 = blockIdx.x * 32, k0 = blockIdx.y * 32;
    int tx = threadIdx.x, ty = threadIdx.y;       // (32, 8)
    #pragma unroll
    for (int i = 0; i < 4; i++)
        t[ty + 8*i][tx] = W[(size_t)(k0 + ty + 8*i) * N + n0 + tx];
    __syncthreads();
    #pragma unroll
    for (int i = 0; i < 4; i++)
        split_store(t[tx][ty + 8*i], Th, Tl, (size_t)(n0 + ty + 8*i) * K + k0 + tx);
}

// V slab of QKV -> VT[z][HD][S]
__global__ void transpose_vt(const bf16* __restrict__ qh, const bf16* __restrict__ ql,
                             bf16* __restrict__ vth, bf16* __restrict__ vtl) {
    __shared__ bf16 th[32][33], tl[32][33];
    int z = blockIdx.z;
    int s0 = blockIdx.x * 32, d0 = blockIdx.y * 32;
    int tx = threadIdx.x, ty = threadIdx.y;       // (32, 8)
    size_t base = (size_t)z * S_ * 192 + 128;
    #pragma unroll
    for (int i = 0; i < 4; i++) {
        size_t gi = base + (size_t)(s0 + ty + 8*i) * 192 + d0 + tx;
        th[ty + 8*i][tx] = qh[gi];
        tl[ty + 8*i][tx] = ql[gi];
    }
    __syncthreads();
    size_t ob = (size_t)z * HD_ * S_;
    #pragma unroll
    for (int i = 0; i < 4; i++) {
        size_t oi = ob + (size_t)(d0 + ty + 8*i) * S_ + s0 + tx;
        vth[oi] = th[tx][ty + 8*i];
        vtl[oi] = tl[tx][ty + 8*i];
    }
}

// ===================== mma.sync GEMM ========================================
// C[M,N](batch z) = A[M,K] * B[N,K]^T, split-bf16 3-product, fp32 accum.
// EPI: 0 fp32 (+bias if non-null), 1 QK (alpha, tile-skip via g_len),
//      2 split-bf16 out, 3 bias+relu -> split-bf16 out
template<int BN, int EPI>
__global__ __launch_bounds__(256, 1)
void gemm_mma(int M, int N, int K,
              const bf16* __restrict__ Ah_, const bf16* __restrict__ Al_, int lda, size_t sA,
              const bf16* __restrict__ Bh_, const bf16* __restrict__ Bl_, int ldb, size_t sB,
              float* __restrict__ Cf, bf16* __restrict__ Ch, bf16* __restrict__ Cl,
              int ldc, size_t sC, const float* __restrict__ bias, float alpha, int dynk)
{
    constexpr int WARPS_N = (BN == 128) ? 4 : 2;
    constexpr int WARPS_M = 8 / WARPS_N;
    constexpr int WM = 128 / WARPS_M;             // 64 or 32
    constexpr int WN = BN / WARPS_N;              // 32
    constexpr int MI = WM / 16;                   // 4 or 2
    constexpr int NI = WN / 8;                    // 4
    constexpr int STR = 40;                       // bf16 elems per smem row (80B)
    constexpr int OFF_AL = 128 * STR;
    constexpr int OFF_BH = 256 * STR;
    constexpr int STG = (256 + 2 * BN) * STR;     // elems per stage

    extern __shared__ __align__(16) bf16 sm[];

    const int z  = blockIdx.z;
    const int bm = blockIdx.y * 128;
    const int bn = blockIdx.x * BN;
    const int tid = threadIdx.x;
    const int wid = tid >> 5, lane = tid & 31;
    const int wm = wid / WARPS_N, wn = wid % WARPS_N;

    int len = S_;
    if (EPI == 1 || dynk) len = g_len[z / H_];
    if (EPI == 1 && (bm >= len || bn >= len)) return;
    const int Keff = dynk ? ((len + 31) & ~31) : K;
    const int KP = Keff / 32;

    const bf16* pAh = Ah_ + (size_t)z * sA + (size_t)bm * lda;
    const bf16* pAl = Al_ + (size_t)z * sA + (size_t)bm * lda;
    const bf16* pBh = Bh_ + (size_t)z * sB + (size_t)bn * ldb;
    const bf16* pBl = Bl_ + (size_t)z * sB + (size_t)bn * ldb;
    const uint32_t smb = smem_u32(sm);

    auto load_stage = [&](int p, int st) {
        const size_t k0 = (size_t)p * 32;
        const uint32_t sb = smb + (uint32_t)st * STG * 2;
        #pragma unroll
        for (int i = tid; i < 128 * 4; i += 256) {
            int r = i >> 2, ch = i & 3;
            uint32_t d = sb + (uint32_t)(r * STR + ch * 8) * 2;
            cp16(d,               pAh + (size_t)r * lda + k0 + ch * 8);
            cp16(d + OFF_AL * 2,  pAl + (size_t)r * lda + k0 + ch * 8);
        }
        #pragma unroll
        for (int i = tid; i < BN * 4; i += 256) {
            int r = i >> 2, ch = i & 3;
            uint32_t d = sb + (uint32_t)(OFF_BH + r * STR + ch * 8) * 2;
            cp16(d,                pBh + (size_t)r * ldb + k0 + ch * 8);
            cp16(d + BN * STR * 2, pBl + (size_t)r * ldb + k0 + ch * 8);
        }
    };

    float c[MI][NI][4];
    #pragma unroll
    for (int i = 0; i < MI; i++)
        #pragma unroll
        for (int j = 0; j < NI; j++)
            #pragma unroll
            for (int q = 0; q < 4; q++) c[i][j][q] = 0.0f;

    load_stage(0, 0); CPC;
    if (KP > 1) { load_stage(1, 1); CPC; }

    for (int p = 0; p < KP; p++) {
        if (p < KP - 1) { CPW1; } else { CPW0; }
        __syncthreads();
        const int st = p & 1;
        const uint32_t sb = smb + (uint32_t)st * STG * 2;

        #pragma unroll
        for (int ks = 0; ks < 2; ks++) {
            const int colo = ks * 16 + (lane >> 4) * 8;
            uint32_t aH[MI][4], aL[MI][4], bH[NI][2], bL[NI][2];
            #pragma unroll
            for (int mi = 0; mi < MI; mi++) {
                int row = wm * WM + mi * 16 + (lane & 15);
                uint32_t ad = sb + (uint32_t)(row * STR + colo) * 2;
                LDSM4(aH[mi][0], aH[mi][1], aH[mi][2], aH[mi][3], ad);
                LDSM4(aL[mi][0], aL[mi][1], aL[mi][2], aL[mi][3], ad + OFF_AL * 2);
            }
            #pragma unroll
            for (int j2 = 0; j2 < NI / 2; j2++) {
                int rowb = wn * WN + j2 * 16 + (lane & 15);
                uint32_t bd = sb + (uint32_t)(OFF_BH + rowb * STR + colo) * 2;
                uint32_t r0, r1, r2, r3;
                LDSM4(r0, r1, r2, r3, bd);
                bH[2*j2][0] = r0; bH[2*j2][1] = r2;
                bH[2*j2+1][0] = r1; bH[2*j2+1][1] = r3;
                LDSM4(r0, r1, r2, r3, bd + BN * STR * 2);
                bL[2*j2][0] = r0; bL[2*j2][1] = r2;
                bL[2*j2+1][0] = r1; bL[2*j2+1][1] = r3;
            }
            #pragma unroll
            for (int mi = 0; mi < MI; mi++)
                #pragma unroll
                for (int nj = 0; nj < NI; nj++) {
                    mma16816(c[mi][nj], aH[mi], bH[nj]);
                    mma16816(c[mi][nj], aH[mi], bL[nj]);
                    mma16816(c[mi][nj], aL[mi], bH[nj]);
                }
        }
        __syncthreads();
        if (p + 2 < KP) { load_stage(p + 2, st); CPC; }
    }

    // ------- epilogue -------
    #pragma unroll
    for (int mi = 0; mi < MI; mi++) {
        const int row = bm + wm * WM + mi * 16 + (lane >> 2);
        #pragma unroll
        for (int nj = 0; nj < NI; nj++) {
            const int col = bn + wn * WN + nj * 8 + 2 * (lane & 3);
            const size_t i0 = (size_t)z * sC + (size_t)row * ldc + col;
            const size_t i1 = i0 + (size_t)8 * ldc;
            float v0 = c[mi][nj][0], v1 = c[mi][nj][1];
            float v2 = c[mi][nj][2], v3 = c[mi][nj][3];
            if (EPI == 0) {
                if (bias) { v0 += bias[col]; v1 += bias[col + 1]; v2 += bias[col]; v3 += bias[col + 1]; }
                Cf[i0] = v0; Cf[i0 + 1] = v1;
                Cf[i1] = v2; Cf[i1 + 1] = v3;
            } else if (EPI == 1) {
                Cf[i0] = v0 * alpha; Cf[i0 + 1] = v1 * alpha;
                Cf[i1] = v2 * alpha; Cf[i1 + 1] = v3 * alpha;
            } else {
                if (EPI == 3) {
                    v0 = fmaxf(v0 + bias[col], 0.0f); v1 = fmaxf(v1 + bias[col + 1], 0.0f);
                    v2 = fmaxf(v2 + bias[col], 0.0f); v3 = fmaxf(v3 + bias[col + 1], 0.0f);
                }
                split_store(v0, Ch, Cl, i0); split_store(v1, Ch, Cl, i0 + 1);
                split_store(v2, Ch, Cl, i1); split_store(v3, Ch, Cl, i1 + 1);
            }
        }
    }
}

// ===================== softmax ==============================================
__device__ __forceinline__ float warpSum(float v) {
    #pragma unroll
    for (int o = 16; o > 0; o >>= 1) v += __shfl_xor_sync(0xffffffffu, v, o);
    return v;
}
__device__ __forceinline__ float warpMax(float v) {
    #pragma unroll
    for (int o = 16; o > 0; o >>= 1) v = fmaxf(v, __shfl_xor_sync(0xffffffffu, v, o));
    return v;
}

__global__ void softmax_rows(const float* __restrict__ Pf, bf16* __restrict__ ph,
                             bf16* __restrict__ plo) {
    const size_t r = blockIdx.x;
    const int q = (int)(r % S_);
    const int b = (int)(r / S_) / H_;
    const int len = g_len[b];
    const float* row = Pf + r * (size_t)S_;
    bf16* oh = ph + r * (size_t)S_;
    bf16* ol = plo + r * (size_t)S_;
    const int t = threadIdx.x;
    const bf16 zb = __float2bfloat16(0.0f);

    if (q >= len) {
        #pragma unroll
        for (int i = 0; i < 8; i++) { oh[t + 256*i] = zb; ol[t + 256*i] = zb; }
        return;
    }
    __shared__ float sm1[8], sm2[8];
    const int lane = t & 31, wid = t >> 5;
    float v[8], mx = -3.4e38f;
    #pragma unroll
    for (int i = 0; i < 8; i++) {
        int cc = t + 256 * i;
        v[i] = (cc < len) ? row[cc] : -3.4e38f;
        mx = fmaxf(mx, v[i]);
    }
    float w = warpMax(mx);
    if (lane == 0) sm1[wid] = w;
    __syncthreads();
    float m = sm1[0];
    #pragma unroll
    for (int i = 1; i < 8; i++) m = fmaxf(m, sm1[i]);
    float s = 0.0f;
    #pragma unroll
    for (int i = 0; i < 8; i++) { float e = __expf(v[i] - m); v[i] = e; s += e; }
    w = warpSum(s);
    if (lane == 0) sm2[wid] = w;
    __syncthreads();
    float tot = 0.0f;
    #pragma unroll
    for (int i = 0; i < 8; i++) tot += sm2[i];
    float inv = 1.0f / tot;
    #pragma unroll
    for (int i = 0; i < 8; i++) split_store(v[i] * inv, oh, ol, (size_t)(t + 256 * i));
}

// ===================== fused add + LayerNorm ================================
__global__ void add_ln(const float* __restrict__ Y, const float* __restrict__ R,
                       const float* __restrict__ g, const float* __restrict__ be,
                       float* __restrict__ outF, bf16* __restrict__ outH,
                       bf16* __restrict__ outL)
{
    const int r = blockIdx.x;
    const float* y = Y + (size_t)r * D_;
    const float* x = R + (size_t)r * D_;
    const int t = threadIdx.x;                    // 128 threads
    const int lane = t & 31, wid = t >> 5;
    __shared__ float sm1[4], sm2[4];
    float v[4], s = 0.0f;
    #pragma unroll
    for (int i = 0; i < 4; i++) { v[i] = y[t + 128*i] + x[t + 128*i]; s += v[i]; }
    float w = warpSum(s);
    if (lane == 0) sm1[wid] = w;
    __syncthreads();
    float mean = (sm1[0] + sm1[1] + sm1[2] + sm1[3]) * (1.0f / D_);
    float vs = 0.0f;
    #pragma unroll
    for (int i = 0; i < 4; i++) { float d = v[i] - mean; vs += d * d; }
    w = warpSum(vs);
    if (lane == 0) sm2[wid] = w;
    __syncthreads();
    float rstd = rsqrtf((sm2[0] + sm2[1] + sm2[2] + sm2[3]) * (1.0f / D_) + EPS_);
    #pragma unroll
    for (int i = 0; i < 4; i++) {
        int cc = t + 128 * i;
        float o = g[cc] * (v[i] - mean) * rstd + be[cc];
        size_t oi = (size_t)r * D_ + cc;
        outF[oi] = o;
        split_store(o, outH, outL, oi);
    }
}

// ===================== launch ===============================================
extern "C" void kernel_launch(void* const* d_in, const int* in_sizes, int n_in,
                              void* d_out, int out_size)
{
    const float* x    = (const float*)d_in[0];
    const unsigned char* mask = (const unsigned char*)d_in[1];
    const float* Wqkv = (const float*)d_in[2];
    const float* Wo   = (const float*)d_in[3];
    const float* bo   = (const float*)d_in[4];
    const float* g1   = (const float*)d_in[5];
    const float* be1  = (const float*)d_in[6];
    const float* W1   = (const float*)d_in[7];
    const float* bf1  = (const float*)d_in[8];
    const float* W2   = (const float*)d_in[9];
    const float* bf2  = (const float*)d_in[10];
    const float* g2   = (const float*)d_in[11];
    const float* be2  = (const float*)d_in[12];
    float* out = (float*)d_out;

    bf16 *xh, *xl, *qh, *ql, *vth, *vtl, *ph, *plo, *ah, *al, *hh, *hl;
    float *Pf, *Yf, *r1, *r2;
    bf16 *wqT[2], *woT[2], *w1T[2], *w2T[2];
    cudaGetSymbolAddress((void**)&xh, g_xh);   cudaGetSymbolAddress((void**)&xl, g_xl);
    cudaGetSymbolAddress((void**)&qh, g_qh);   cudaGetSymbolAddress((void**)&ql, g_ql);
    cudaGetSymbolAddress((void**)&vth, g_vth); cudaGetSymbolAddress((void**)&vtl, g_vtl);
    cudaGetSymbolAddress((void**)&Pf, g_Pf);
    cudaGetSymbolAddress((void**)&ph, g_ph);   cudaGetSymbolAddress((void**)&plo, g_pl);
    cudaGetSymbolAddress((void**)&ah, g_ah);   cudaGetSymbolAddress((void**)&al, g_al);
    cudaGetSymbolAddress((void**)&Yf, g_Yf);
    cudaGetSymbolAddress((void**)&r1, g_r1);   cudaGetSymbolAddress((void**)&r2, g_r2);
    cudaGetSymbolAddress((void**)&hh, g_hh);   cudaGetSymbolAddress((void**)&hl, g_hl);
    cudaGetSymbolAddress((void**)&wqT[0], g_wqT); cudaGetSymbolAddress((void**)&woT[0], g_woT);
    cudaGetSymbolAddress((void**)&w1T[0], g_w1T); cudaGetSymbolAddress((void**)&w2T[0], g_w2T);
    wqT[1] = wqT[0] + L_*3*D_*D_; woT[1] = woT[0] + L_*D_*D_;
    w1T[1] = w1T[0] + L_*FF_*D_;  w2T[1] = w2T[0] + L_*D_*FF_;

    const int SMB128 = 2 * (256 + 256) * 40 * 2;   // 81920
    const int SMB64  = 2 * (256 + 128) * 40 * 2;   // 61440
    cudaFuncSetAttribute(gemm_mma<128,0>, cudaFuncAttributeMaxDynamicSharedMemorySize, SMB128);
    cudaFuncSetAttribute(gemm_mma<128,1>, cudaFuncAttributeMaxDynamicSharedMemorySize, SMB128);
    cudaFuncSetAttribute(gemm_mma<128,2>, cudaFuncAttributeMaxDynamicSharedMemorySize, SMB128);
    cudaFuncSetAttribute(gemm_mma<128,3>, cudaFuncAttributeMaxDynamicSharedMemorySize, SMB128);
    cudaFuncSetAttribute(gemm_mma<64,2>,  cudaFuncAttributeMaxDynamicSharedMemorySize, SMB64);

    prep_mask<<<1, 256>>>(mask);
    convert_split<<<(B_*S_*D_ + 255)/256, 256>>>(x, xh, xl, B_*S_*D_);

    dim3 tb(32, 8);
    for (int l = 0; l < L_; l++) {
        transpose_split<<<dim3(3*D_/32, D_/32), tb>>>(Wqkv + (size_t)l*D_*3*D_,
            wqT[0] + (size_t)l*3*D_*D_, wqT[1] + (size_t)l*3*D_*D_, D_, 3*D_);
        transpose_split<<<dim3(D_/32, D_/32), tb>>>(Wo + (size_t)l*D_*D_,
            woT[0] + (size_t)l*D_*D_, woT[1] + (size_t)l*D_*D_, D_, D_);
        transpose_split<<<dim3(FF_/32, D_/32), tb>>>(W1 + (size_t)l*D_*FF_,
            w1T[0] + (size_t)l*FF_*D_, w1T[1] + (size_t)l*FF_*D_, D_, FF_);
        transpose_split<<<dim3(D_/32, FF_/32), tb>>>(W2 + (size_t)l*FF_*D_,
            w2T[0] + (size_t)l*D_*FF_, w2T[1] + (size_t)l*D_*FF_, FF_, D_);
    }

    const int M = B_ * S_;
    for (int l = 0; l < L_; l++) {
        const float* curF = (l == 0) ? x : r2;

        // QKV = x @ Wqkv -> split bf16
        gemm_mma<128,2><<<dim3(3*D_/128, M/128, 1), 256, SMB128>>>(
            M, 3*D_, D_, xh, xl, D_, 0,
            wqT[0] + (size_t)l*3*D_*D_, wqT[1] + (size_t)l*3*D_*D_, D_, 0,
            nullptr, qh, ql, 3*D_, 0, nullptr, 1.0f, 0);

        transpose_vt<<<dim3(S_/32, HD_/32, B_*H_), tb>>>(qh, ql, vth, vtl);

        // P = Q K^T / 8 (tile-skipped)
        gemm_mma<128,1><<<dim3(S_/128, S_/128, B_*H_), 256, SMB128>>>(
            S_, S_, HD_, qh, ql, 3*HD_, (size_t)S_*3*HD_,
            qh + HD_, ql + HD_, 3*HD_, (size_t)S_*3*HD_,
            Pf, nullptr, nullptr, S_, (size_t)S_*S_, nullptr, 0.125f, 0);

        softmax_rows<<<B_*H_*S_, 256>>>(Pf, ph, plo);

        // attn = P @ V (K truncated to len)
        gemm_mma<64,2><<<dim3(1, S_/128, B_*H_), 256, SMB64>>>(
            S_, HD_, S_, ph, plo, S_, (size_t)S_*S_,
            vth, vtl, S_, (size_t)HD_*S_,
            nullptr, ah, al, HD_, (size_t)S_*HD_, nullptr, 1.0f, 1);

        // Y = attn @ Wo + bo
        gemm_mma<128,0><<<dim3(D_/128, M/128, 1), 256, SMB128>>>(
            M, D_, D_, ah, al, D_, 0,
            woT[0] + (size_t)l*D_*D_, woT[1] + (size_t)l*D_*D_, D_, 0,
            Yf, nullptr, nullptr, D_, 0, bo + (size_t)l*D_, 1.0f, 0);

        add_ln<<<M, 128>>>(Yf, curF, g1 + (size_t)l*D_, be1 + (size_t)l*D_, r1, xh, xl);

        // H = relu(x @ W1 + bf1) -> split
        gemm_mma<128,3><<<dim3(FF_/128, M/128, 1), 256, SMB128>>>(
            M, FF_, D_, xh, xl, D_, 0,
            w1T[0] + (size_t)l*FF_*D_, w1T[1] + (size_t)l*FF_*D_, D_, 0,
            nullptr, hh, hl, FF_, 0, bf1 + (size_t)l*FF_, 1.0f, 0);

        // Y = H @ W2 + bf2
        gemm_mma<128,0><<<dim3(D_/128, M/128, 1), 256, SMB128>>>(
            M, D_, FF_, hh, hl, FF_, 0,
            w2T[0] + (size_t)l*D_*FF_, w2T[1] + (size_t)l*D_*FF_, FF_, 0,
            Yf, nullptr, nullptr, D_, 0, bf2 + (size_t)l*D_, 1.0f, 0);

        float* dst = (l == L_ - 1) ? out : r2;
        add_ln<<<M, 128>>>(Yf, r1, g2 + (size_t)l*D_, be2 + (size_t)l*D_, dst, xh, xl);
    }
    (void)in_sizes; (void)n_in; (void)out_size;
}

// round 5
// speedup vs baseline: 3.1189x; 1.3339x over previous
#include <cuda_runtime.h>
#include <cuda_bf16.h>
#include <cstdint>
#include <cstddef>

#define B_  2
#define S_  2048
#define D_  512
#define H_  8
#define HD_ 64
#define FF_ 2048
#define L_  2
#define EPS_ 1e-5f

typedef __nv_bfloat16 bf16;

// ===================== PTX helpers (non-'a' gated only) =====================
__device__ __forceinline__ uint32_t smem_u32(const void* p) {
    uint32_t a;
    asm("{ .reg .u64 t; cvta.to.shared.u64 t, %1; cvt.u32.u64 %0, t; }" : "=r"(a) : "l"(p));
    return a;
}
__device__ __forceinline__ void cp16(uint32_t dst, const void* src) {
    asm volatile("cp.async.cg.shared.global [%0], [%1], 16;" :: "r"(dst), "l"(src));
}
#define CPC  asm volatile("cp.async.commit_group;" ::: "memory")
#define CPW1 asm volatile("cp.async.wait_group 1;" ::: "memory")
#define CPW0 asm volatile("cp.async.wait_group 0;" ::: "memory")
#define LDSM4(r0, r1, r2, r3, a) \
    asm volatile("ldmatrix.sync.aligned.m8n8.x4.shared.b16 {%0,%1,%2,%3}, [%4];" \
                 : "=r"(r0), "=r"(r1), "=r"(r2), "=r"(r3) : "r"(a))
#define LDSM4T(r0, r1, r2, r3, a) \
    asm volatile("ldmatrix.sync.aligned.m8n8.x4.trans.shared.b16 {%0,%1,%2,%3}, [%4];" \
                 : "=r"(r0), "=r"(r1), "=r"(r2), "=r"(r3) : "r"(a))

__device__ __forceinline__ void mma16816(float* c, const uint32_t* a, const uint32_t* b) {
    asm volatile("mma.sync.aligned.m16n8k16.row.col.f32.bf16.bf16.f32 "
                 "{%0,%1,%2,%3}, {%4,%5,%6,%7}, {%8,%9}, {%0,%1,%2,%3};"
                 : "+f"(c[0]), "+f"(c[1]), "+f"(c[2]), "+f"(c[3])
                 : "r"(a[0]), "r"(a[1]), "r"(a[2]), "r"(a[3]), "r"(b[0]), "r"(b[1]));
}

__device__ __forceinline__ uint32_t packbf(float a, float b) {
    __nv_bfloat162 t = __floats2bfloat162_rn(a, b);
    return *(uint32_t*)&t;
}

// ===================== device scratch =======================================
__device__ int  g_len[B_];
__device__ bf16 g_xh[B_*S_*D_],  g_xl[B_*S_*D_];
__device__ bf16 g_qh[B_*S_*3*D_], g_ql[B_*S_*3*D_];
__device__ bf16 g_ah[B_*S_*D_], g_al[B_*S_*D_];
__device__ float g_Yf[B_*S_*D_], g_r1[B_*S_*D_], g_r2[B_*S_*D_];
__device__ bf16 g_hh[B_*S_*FF_], g_hl[B_*S_*FF_];
__device__ bf16 g_wqT[2][L_*3*D_*D_];
__device__ bf16 g_woT[2][L_*D_*D_];
__device__ bf16 g_w1T[2][L_*FF_*D_];
__device__ bf16 g_w2T[2][L_*D_*FF_];

__device__ __forceinline__ void split_store(float v, bf16* H, bf16* L, size_t i) {
    bf16 h = __float2bfloat16(v);
    H[i] = h;
    L[i] = __float2bfloat16(v - __bfloat162float(h));
}

// ===================== mask prep (validated R1) =============================
__global__ void prep_mask(const unsigned char* __restrict__ m8) {
    __shared__ int s_cnt, s_bad;
    const int* m32 = (const int*)m8;
    for (int b = 0; b < B_; b++) {
        if (threadIdx.x == 0) { s_cnt = 0; s_bad = 0; }
        __syncthreads();
        int local = 0;
        for (int j = threadIdx.x; j < S_; j += blockDim.x)
            local += (m8[b * S_ + j] != 0) ? 1 : 0;
        atomicAdd(&s_cnt, local);
        __syncthreads();
        int c = s_cnt, bad = 0;
        for (int j = threadIdx.x; j < S_; j += blockDim.x) {
            int v = (m8[b * S_ + j] != 0) ? 1 : 0;
            if (v != ((j < c) ? 1 : 0)) bad = 1;
        }
        if (bad) atomicOr(&s_bad, 1);
        __syncthreads();
        if (s_bad != 0 || c < S_ / 2) {
            if (threadIdx.x == 0) s_cnt = 0;
            __syncthreads();
            local = 0;
            for (int j = threadIdx.x; j < S_; j += blockDim.x)
                local += (m32[b * S_ + j] != 0) ? 1 : 0;
            atomicAdd(&s_cnt, local);
            __syncthreads();
            c = s_cnt;
        }
        if (threadIdx.x == 0) g_len[b] = c;
        __syncthreads();
    }
}

// ===================== conversions ==========================================
__global__ void convert_split(const float* __restrict__ in, bf16* __restrict__ hi,
                              bf16* __restrict__ lo, int n) {
    int i = blockIdx.x * blockDim.x + threadIdx.x;
    if (i < n) split_store(in[i], hi, lo, i);
}

// W[K,N] fp32 -> T[N,K] split bf16
__global__ void transpose_split(const float* __restrict__ W, bf16* __restrict__ Th,
                                bf16* __restrict__ Tl, int K, int N) {
    __shared__ float t[32][33];
    int n0 = blockIdx.x * 32, k0 = blockIdx.y * 32;
    int tx = threadIdx.x, ty = threadIdx.y;       // (32, 8)
    #pragma unroll
    for (int i = 0; i < 4; i++)
        t[ty + 8*i][tx] = W[(size_t)(k0 + ty + 8*i) * N + n0 + tx];
    __syncthreads();
    #pragma unroll
    for (int i = 0; i < 4; i++)
        split_store(t[tx][ty + 8*i], Th, Tl, (size_t)(n0 + ty + 8*i) * K + k0 + tx);
}

// ===================== mma.sync GEMM (validated R4) =========================
// EPI: 0 fp32 (+bias), 2 split-bf16 out, 3 bias+relu -> split-bf16 out
template<int BN, int EPI>
__global__ __launch_bounds__(256, 1)
void gemm_mma(int M, int N, int K,
              const bf16* __restrict__ Ah_, const bf16* __restrict__ Al_, int lda, size_t sA,
              const bf16* __restrict__ Bh_, const bf16* __restrict__ Bl_, int ldb, size_t sB,
              float* __restrict__ Cf, bf16* __restrict__ Ch, bf16* __restrict__ Cl,
              int ldc, size_t sC, const float* __restrict__ bias)
{
    constexpr int WARPS_N = (BN == 128) ? 4 : 2;
    constexpr int WARPS_M = 8 / WARPS_N;
    constexpr int WM = 128 / WARPS_M;
    constexpr int WN = BN / WARPS_N;
    constexpr int MI = WM / 16;
    constexpr int NI = WN / 8;
    constexpr int STR = 40;
    constexpr int OFF_AL = 128 * STR;
    constexpr int OFF_BH = 256 * STR;
    constexpr int STG = (256 + 2 * BN) * STR;

    extern __shared__ __align__(16) bf16 sm[];

    const int z  = blockIdx.z;
    const int bm = blockIdx.y * 128;
    const int bn = blockIdx.x * BN;
    const int tid = threadIdx.x;
    const int wid = tid >> 5, lane = tid & 31;
    const int wm = wid / WARPS_N, wn = wid % WARPS_N;

    const int KP = K / 32;

    const bf16* pAh = Ah_ + (size_t)z * sA + (size_t)bm * lda;
    const bf16* pAl = Al_ + (size_t)z * sA + (size_t)bm * lda;
    const bf16* pBh = Bh_ + (size_t)z * sB + (size_t)bn * ldb;
    const bf16* pBl = Bl_ + (size_t)z * sB + (size_t)bn * ldb;
    const uint32_t smb = smem_u32(sm);

    auto load_stage = [&](int p, int st) {
        const size_t k0 = (size_t)p * 32;
        const uint32_t sb = smb + (uint32_t)st * STG * 2;
        #pragma unroll
        for (int i = tid; i < 128 * 4; i += 256) {
            int r = i >> 2, ch = i & 3;
            uint32_t d = sb + (uint32_t)(r * STR + ch * 8) * 2;
            cp16(d,               pAh + (size_t)r * lda + k0 + ch * 8);
            cp16(d + OFF_AL * 2,  pAl + (size_t)r * lda + k0 + ch * 8);
        }
        #pragma unroll
        for (int i = tid; i < BN * 4; i += 256) {
            int r = i >> 2, ch = i & 3;
            uint32_t d = sb + (uint32_t)(OFF_BH + r * STR + ch * 8) * 2;
            cp16(d,                pBh + (size_t)r * ldb + k0 + ch * 8);
            cp16(d + BN * STR * 2, pBl + (size_t)r * ldb + k0 + ch * 8);
        }
    };

    float c[MI][NI][4];
    #pragma unroll
    for (int i = 0; i < MI; i++)
        #pragma unroll
        for (int j = 0; j < NI; j++)
            #pragma unroll
            for (int q = 0; q < 4; q++) c[i][j][q] = 0.0f;

    load_stage(0, 0); CPC;
    if (KP > 1) { load_stage(1, 1); CPC; }

    for (int p = 0; p < KP; p++) {
        if (p < KP - 1) { CPW1; } else { CPW0; }
        __syncthreads();
        const int st = p & 1;
        const uint32_t sb = smb + (uint32_t)st * STG * 2;

        #pragma unroll
        for (int ks = 0; ks < 2; ks++) {
            const int colo = ks * 16 + (lane >> 4) * 8;
            uint32_t aH[MI][4], aL[MI][4], bH[NI][2], bL[NI][2];
            #pragma unroll
            for (int mi = 0; mi < MI; mi++) {
                int row = wm * WM + mi * 16 + (lane & 15);
                uint32_t ad = sb + (uint32_t)(row * STR + colo) * 2;
                LDSM4(aH[mi][0], aH[mi][1], aH[mi][2], aH[mi][3], ad);
                LDSM4(aL[mi][0], aL[mi][1], aL[mi][2], aL[mi][3], ad + OFF_AL * 2);
            }
            #pragma unroll
            for (int j2 = 0; j2 < NI / 2; j2++) {
                int rowb = wn * WN + j2 * 16 + (lane & 15);
                uint32_t bd = sb + (uint32_t)(OFF_BH + rowb * STR + colo) * 2;
                uint32_t r0, r1, r2, r3;
                LDSM4(r0, r1, r2, r3, bd);
                bH[2*j2][0] = r0; bH[2*j2][1] = r2;
                bH[2*j2+1][0] = r1; bH[2*j2+1][1] = r3;
                LDSM4(r0, r1, r2, r3, bd + BN * STR * 2);
                bL[2*j2][0] = r0; bL[2*j2][1] = r2;
                bL[2*j2+1][0] = r1; bL[2*j2+1][1] = r3;
            }
            #pragma unroll
            for (int mi = 0; mi < MI; mi++)
                #pragma unroll
                for (int nj = 0; nj < NI; nj++) {
                    mma16816(c[mi][nj], aH[mi], bH[nj]);
                    mma16816(c[mi][nj], aH[mi], bL[nj]);
                    mma16816(c[mi][nj], aL[mi], bH[nj]);
                }
        }
        __syncthreads();
        if (p + 2 < KP) { load_stage(p + 2, st); CPC; }
    }

    #pragma unroll
    for (int mi = 0; mi < MI; mi++) {
        const int row = bm + wm * WM + mi * 16 + (lane >> 2);
        #pragma unroll
        for (int nj = 0; nj < NI; nj++) {
            const int col = bn + wn * WN + nj * 8 + 2 * (lane & 3);
            const size_t i0 = (size_t)z * sC + (size_t)row * ldc + col;
            const size_t i1 = i0 + (size_t)8 * ldc;
            float v0 = c[mi][nj][0], v1 = c[mi][nj][1];
            float v2 = c[mi][nj][2], v3 = c[mi][nj][3];
            if (EPI == 0) {
                if (bias) { v0 += bias[col]; v1 += bias[col + 1]; v2 += bias[col]; v3 += bias[col + 1]; }
                Cf[i0] = v0; Cf[i0 + 1] = v1;
                Cf[i1] = v2; Cf[i1 + 1] = v3;
            } else {
                if (EPI == 3) {
                    v0 = fmaxf(v0 + bias[col], 0.0f); v1 = fmaxf(v1 + bias[col + 1], 0.0f);
                    v2 = fmaxf(v2 + bias[col], 0.0f); v3 = fmaxf(v3 + bias[col + 1], 0.0f);
                }
                split_store(v0, Ch, Cl, i0); split_store(v1, Ch, Cl, i0 + 1);
                split_store(v2, Ch, Cl, i1); split_store(v3, Ch, Cl, i1 + 1);
            }
        }
    }
}

// ===================== fused flash attention ================================
// grid (S/128, B*H), 256 threads (8 warps, 16 q-rows each).
// QKV layout (reference reinterpretation): head z at flat z*S*192; within a
// position: Q [0,64), K [64,128), V [128,192).
__global__ __launch_bounds__(256, 1)
void flash_attn(const bf16* __restrict__ qh, const bf16* __restrict__ ql,
                bf16* __restrict__ ah, bf16* __restrict__ al)
{
    constexpr int STR = 72;                 // padded row stride (bank-safe)
    constexpr int PANEL = 128 * STR;        // elems per 128x64 panel
    extern __shared__ __align__(16) bf16 sm[];

    const int z   = blockIdx.y;
    const int qt  = blockIdx.x * 128;
    const int len = g_len[z / H_];
    const int nkt = (len + 127) >> 7;
    const int tid = threadIdx.x, wid = tid >> 5, lane = tid & 31;
    const uint32_t smb = smem_u32(sm);
    const size_t hbase = (size_t)z * S_ * 192;

    // ---- async load Q tile (group 0, together with stage 0) ----
    for (int i = tid; i < 128 * 8; i += 256) {
        int r = i >> 3, ch = i & 7;
        uint32_t d = smb + (uint32_t)(r * STR + ch * 8) * 2;
        const size_t g = hbase + (size_t)(qt + r) * 192 + ch * 8;
        cp16(d, qh + g);
        cp16(d + PANEL * 2, ql + g);
    }
    auto load_kv = [&](int j, int st) {
        const uint32_t sb = smb + (uint32_t)(2 * PANEL + st * 4 * PANEL) * 2;
        for (int i = tid; i < 128 * 8; i += 256) {
            int r = i >> 3, ch = i & 7;
            uint32_t d = sb + (uint32_t)(r * STR + ch * 8) * 2;
            const size_t g = hbase + (size_t)(j * 128 + r) * 192 + ch * 8;
            cp16(d,                 qh + g + 64);    // K hi
            cp16(d + PANEL * 2,     ql + g + 64);    // K lo
            cp16(d + 2 * PANEL * 2, qh + g + 128);   // V hi
            cp16(d + 3 * PANEL * 2, ql + g + 128);   // V lo
        }
    };
    load_kv(0, 0); CPC;
    if (nkt > 1) load_kv(1, 1);
    CPC;
    CPW1; __syncthreads();

    // ---- preload Q fragments ----
    uint32_t qH[4][4], qL[4][4];
    {
        int row = wid * 16 + (lane & 15);
        #pragma unroll
        for (int kc = 0; kc < 4; kc++) {
            uint32_t a = smb + (uint32_t)(row * STR + kc * 16 + ((lane >> 4) << 3)) * 2;
            LDSM4(qH[kc][0], qH[kc][1], qH[kc][2], qH[kc][3], a);
            LDSM4(qL[kc][0], qL[kc][1], qL[kc][2], qL[kc][3], a + PANEL * 2);
        }
    }

    float m0 = -1e30f, m1 = -1e30f, l0 = 0.0f, l1 = 0.0f;
    float o[8][4];
    #pragma unroll
    for (int t = 0; t < 8; t++)
        #pragma unroll
        for (int q = 0; q < 4; q++) o[t][q] = 0.0f;

    for (int j = 0; j < nkt; j++) {
        if (j > 0) {
            if (j + 1 < nkt) { CPW1; } else { CPW0; }
            __syncthreads();
        }
        const int st = j & 1;
        const uint32_t kb = smb + (uint32_t)(2 * PANEL + st * 4 * PANEL) * 2;

        // ---- S = Q K^T (split 3-product) ----
        float s[16][4];
        #pragma unroll
        for (int t = 0; t < 16; t++)
            #pragma unroll
            for (int q = 0; q < 4; q++) s[t][q] = 0.0f;

        #pragma unroll
        for (int kc = 0; kc < 4; kc++) {
            #pragma unroll
            for (int g = 0; g < 8; g++) {
                int rowb = g * 16 + (lane & 15);
                uint32_t ad = kb + (uint32_t)(rowb * STR + kc * 16 + ((lane >> 4) << 3)) * 2;
                uint32_t h0, h1, h2, h3, e0, e1, e2, e3;
                LDSM4(h0, h1, h2, h3, ad);
                LDSM4(e0, e1, e2, e3, ad + PANEL * 2);
                uint32_t bh0[2] = {h0, h2}, bh1[2] = {h1, h3};
                uint32_t bl0[2] = {e0, e2}, bl1[2] = {e1, e3};
                mma16816(s[2*g],     qH[kc], bh0);
                mma16816(s[2*g],     qH[kc], bl0);
                mma16816(s[2*g],     qL[kc], bh0);
                mma16816(s[2*g+1],   qH[kc], bh1);
                mma16816(s[2*g+1],   qH[kc], bl1);
                mma16816(s[2*g+1],   qL[kc], bh1);
            }
        }

        // ---- scale + column mask ----
        #pragma unroll
        for (int t = 0; t < 16; t++)
            #pragma unroll
            for (int q = 0; q < 4; q++) s[t][q] *= 0.125f;
        if ((j == nkt - 1) && (len & 127)) {
            #pragma unroll
            for (int t = 0; t < 16; t++) {
                int col = j * 128 + t * 8 + 2 * (lane & 3);
                if (col     >= len) { s[t][0] = -1e9f; s[t][2] = -1e9f; }
                if (col + 1 >= len) { s[t][1] = -1e9f; s[t][3] = -1e9f; }
            }
        }

        // ---- online softmax ----
        float mx0 = -1e30f, mx1 = -1e30f;
        #pragma unroll
        for (int t = 0; t < 16; t++) {
            mx0 = fmaxf(mx0, fmaxf(s[t][0], s[t][1]));
            mx1 = fmaxf(mx1, fmaxf(s[t][2], s[t][3]));
        }
        mx0 = fmaxf(mx0, __shfl_xor_sync(0xffffffffu, mx0, 1));
        mx0 = fmaxf(mx0, __shfl_xor_sync(0xffffffffu, mx0, 2));
        mx1 = fmaxf(mx1, __shfl_xor_sync(0xffffffffu, mx1, 1));
        mx1 = fmaxf(mx1, __shfl_xor_sync(0xffffffffu, mx1, 2));
        float mn0 = fmaxf(m0, mx0), mn1 = fmaxf(m1, mx1);
        float sc0 = __expf(m0 - mn0), sc1 = __expf(m1 - mn1);
        m0 = mn0; m1 = mn1;
        float sum0 = 0.0f, sum1 = 0.0f;
        #pragma unroll
        for (int t = 0; t < 16; t++) {
            s[t][0] = __expf(s[t][0] - mn0); sum0 += s[t][0];
            s[t][1] = __expf(s[t][1] - mn0); sum0 += s[t][1];
            s[t][2] = __expf(s[t][2] - mn1); sum1 += s[t][2];
            s[t][3] = __expf(s[t][3] - mn1); sum1 += s[t][3];
        }
        sum0 += __shfl_xor_sync(0xffffffffu, sum0, 1);
        sum0 += __shfl_xor_sync(0xffffffffu, sum0, 2);
        sum1 += __shfl_xor_sync(0xffffffffu, sum1, 1);
        sum1 += __shfl_xor_sync(0xffffffffu, sum1, 2);
        l0 = l0 * sc0 + sum0;
        l1 = l1 * sc1 + sum1;
        #pragma unroll
        for (int t = 0; t < 8; t++) {
            o[t][0] *= sc0; o[t][1] *= sc0;
            o[t][2] *= sc1; o[t][3] *= sc1;
        }

        // ---- O += P V (P from registers, split; V via ldmatrix.trans) ----
        #pragma unroll
        for (int kc = 0; kc < 8; kc++) {
            uint32_t pH[4], pL[4];
            {
                float a0 = s[2*kc][0],   a1 = s[2*kc][1];
                float a2 = s[2*kc][2],   a3 = s[2*kc][3];
                float b0 = s[2*kc+1][0], b1 = s[2*kc+1][1];
                float b2 = s[2*kc+1][2], b3 = s[2*kc+1][3];
                pH[0] = packbf(a0, a1); pH[1] = packbf(a2, a3);
                pH[2] = packbf(b0, b1); pH[3] = packbf(b2, b3);
                float ra0 = a0 - __bfloat162float(__float2bfloat16(a0));
                float ra1 = a1 - __bfloat162float(__float2bfloat16(a1));
                float ra2 = a2 - __bfloat162float(__float2bfloat16(a2));
                float ra3 = a3 - __bfloat162float(__float2bfloat16(a3));
                float rb0 = b0 - __bfloat162float(__float2bfloat16(b0));
                float rb1 = b1 - __bfloat162float(__float2bfloat16(b1));
                float rb2 = b2 - __bfloat162float(__float2bfloat16(b2));
                float rb3 = b3 - __bfloat162float(__float2bfloat16(b3));
                pL[0] = packbf(ra0, ra1); pL[1] = packbf(ra2, ra3);
                pL[2] = packbf(rb0, rb1); pL[3] = packbf(rb2, rb3);
            }
            #pragma unroll
            for (int g = 0; g < 4; g++) {
                int krow = kc * 16 + ((lane >> 3) & 1) * 8 + (lane & 7);
                int ncol = g * 16 + ((lane >> 4) << 3);
                uint32_t ad = kb + (uint32_t)(2 * PANEL + krow * STR + ncol) * 2;
                uint32_t h0, h1, h2, h3, e0, e1, e2, e3;
                LDSM4T(h0, h1, h2, h3, ad);
                LDSM4T(e0, e1, e2, e3, ad + PANEL * 2);
                uint32_t vh0[2] = {h0, h1}, vh1[2] = {h2, h3};
                uint32_t vl0[2] = {e0, e1}, vl1[2] = {e2, e3};
                mma16816(o[2*g],   pH, vh0);
                mma16816(o[2*g],   pH, vl0);
                mma16816(o[2*g],   pL, vh0);
                mma16816(o[2*g+1], pH, vh1);
                mma16816(o[2*g+1], pH, vl1);
                mma16816(o[2*g+1], pL, vh1);
            }
        }
        __syncthreads();
        if (j + 2 < nkt) load_kv(j + 2, st);
        CPC;
    }

    // ---- finalize: normalize, zero masked query rows, split-store ----
    const int q0 = qt + wid * 16 + (lane >> 2);
    const int q1 = q0 + 8;
    const float inv0 = (q0 < len) ? (1.0f / l0) : 0.0f;
    const float inv1 = (q1 < len) ? (1.0f / l1) : 0.0f;
    const size_t b0 = (size_t)z * S_ * HD_ + (size_t)q0 * HD_;
    const size_t b1 = (size_t)z * S_ * HD_ + (size_t)q1 * HD_;
    #pragma unroll
    for (int t = 0; t < 8; t++) {
        int col = t * 8 + 2 * (lane & 3);
        float v0 = o[t][0] * inv0, v1 = o[t][1] * inv0;
        float v2 = o[t][2] * inv1, v3 = o[t][3] * inv1;
        float h0 = __bfloat162float(__float2bfloat16(v0));
        float h1 = __bfloat162float(__float2bfloat16(v1));
        float h2 = __bfloat162float(__float2bfloat16(v2));
        float h3 = __bfloat162float(__float2bfloat16(v3));
        *(uint32_t*)(ah + b0 + col) = packbf(v0, v1);
        *(uint32_t*)(al + b0 + col) = packbf(v0 - h0, v1 - h1);
        *(uint32_t*)(ah + b1 + col) = packbf(v2, v3);
        *(uint32_t*)(al + b1 + col) = packbf(v2 - h2, v3 - h3);
    }
}

// ===================== reductions / layernorm ===============================
__device__ __forceinline__ float warpSum(float v) {
    #pragma unroll
    for (int o = 16; o > 0; o >>= 1) v += __shfl_xor_sync(0xffffffffu, v, o);
    return v;
}

__global__ void add_ln(const float* __restrict__ Y, const float* __restrict__ R,
                       const float* __restrict__ g, const float* __restrict__ be,
                       float* __restrict__ outF, bf16* __restrict__ outH,
                       bf16* __restrict__ outL)
{
    const int r = blockIdx.x;
    const float* y = Y + (size_t)r * D_;
    const float* x = R + (size_t)r * D_;
    const int t = threadIdx.x;                    // 128 threads
    const int lane = t & 31, wid = t >> 5;
    __shared__ float sm1[4], sm2[4];
    float v[4], s = 0.0f;
    #pragma unroll
    for (int i = 0; i < 4; i++) { v[i] = y[t + 128*i] + x[t + 128*i]; s += v[i]; }
    float w = warpSum(s);
    if (lane == 0) sm1[wid] = w;
    __syncthreads();
    float mean = (sm1[0] + sm1[1] + sm1[2] + sm1[3]) * (1.0f / D_);
    float vs = 0.0f;
    #pragma unroll
    for (int i = 0; i < 4; i++) { float d = v[i] - mean; vs += d * d; }
    w = warpSum(vs);
    if (lane == 0) sm2[wid] = w;
    __syncthreads();
    float rstd = rsqrtf((sm2[0] + sm2[1] + sm2[2] + sm2[3]) * (1.0f / D_) + EPS_);
    #pragma unroll
    for (int i = 0; i < 4; i++) {
        int cc = t + 128 * i;
        float o = g[cc] * (v[i] - mean) * rstd + be[cc];
        size_t oi = (size_t)r * D_ + cc;
        outF[oi] = o;
        split_store(o, outH, outL, oi);
    }
}

// ===================== launch ===============================================
extern "C" void kernel_launch(void* const* d_in, const int* in_sizes, int n_in,
                              void* d_out, int out_size)
{
    const float* x    = (const float*)d_in[0];
    const unsigned char* mask = (const unsigned char*)d_in[1];
    const float* Wqkv = (const float*)d_in[2];
    const float* Wo   = (const float*)d_in[3];
    const float* bo   = (const float*)d_in[4];
    const float* g1   = (const float*)d_in[5];
    const float* be1  = (const float*)d_in[6];
    const float* W1   = (const float*)d_in[7];
    const float* bf1  = (const float*)d_in[8];
    const float* W2   = (const float*)d_in[9];
    const float* bf2  = (const float*)d_in[10];
    const float* g2   = (const float*)d_in[11];
    const float* be2  = (const float*)d_in[12];
    float* out = (float*)d_out;

    bf16 *xh, *xl, *qh, *ql, *ah, *al, *hh, *hl;
    float *Yf, *r1, *r2;
    bf16 *wqT[2], *woT[2], *w1T[2], *w2T[2];
    cudaGetSymbolAddress((void**)&xh, g_xh);   cudaGetSymbolAddress((void**)&xl, g_xl);
    cudaGetSymbolAddress((void**)&qh, g_qh);   cudaGetSymbolAddress((void**)&ql, g_ql);
    cudaGetSymbolAddress((void**)&ah, g_ah);   cudaGetSymbolAddress((void**)&al, g_al);
    cudaGetSymbolAddress((void**)&Yf, g_Yf);
    cudaGetSymbolAddress((void**)&r1, g_r1);   cudaGetSymbolAddress((void**)&r2, g_r2);
    cudaGetSymbolAddress((void**)&hh, g_hh);   cudaGetSymbolAddress((void**)&hl, g_hl);
    cudaGetSymbolAddress((void**)&wqT[0], g_wqT); cudaGetSymbolAddress((void**)&woT[0], g_woT);
    cudaGetSymbolAddress((void**)&w1T[0], g_w1T); cudaGetSymbolAddress((void**)&w2T[0], g_w2T);
    wqT[1] = wqT[0] + L_*3*D_*D_; woT[1] = woT[0] + L_*D_*D_;
    w1T[1] = w1T[0] + L_*FF_*D_;  w2T[1] = w2T[0] + L_*D_*FF_;

    const int SMB128 = 2 * (256 + 256) * 40 * 2;   // 81920
    const int SMFL   = 10 * 128 * 72 * 2;          // 184320
    cudaFuncSetAttribute(gemm_mma<128,0>, cudaFuncAttributeMaxDynamicSharedMemorySize, SMB128);
    cudaFuncSetAttribute(gemm_mma<128,2>, cudaFuncAttributeMaxDynamicSharedMemorySize, SMB128);
    cudaFuncSetAttribute(gemm_mma<128,3>, cudaFuncAttributeMaxDynamicSharedMemorySize, SMB128);
    cudaFuncSetAttribute(flash_attn,      cudaFuncAttributeMaxDynamicSharedMemorySize, SMFL);

    prep_mask<<<1, 256>>>(mask);
    convert_split<<<(B_*S_*D_ + 255)/256, 256>>>(x, xh, xl, B_*S_*D_);

    dim3 tb(32, 8);
    for (int l = 0; l < L_; l++) {
        transpose_split<<<dim3(3*D_/32, D_/32), tb>>>(Wqkv + (size_t)l*D_*3*D_,
            wqT[0] + (size_t)l*3*D_*D_, wqT[1] + (size_t)l*3*D_*D_, D_, 3*D_);
        transpose_split<<<dim3(D_/32, D_/32), tb>>>(Wo + (size_t)l*D_*D_,
            woT[0] + (size_t)l*D_*D_, woT[1] + (size_t)l*D_*D_, D_, D_);
        transpose_split<<<dim3(FF_/32, D_/32), tb>>>(W1 + (size_t)l*D_*FF_,
            w1T[0] + (size_t)l*FF_*D_, w1T[1] + (size_t)l*FF_*D_, D_, FF_);
        transpose_split<<<dim3(D_/32, FF_/32), tb>>>(W2 + (size_t)l*FF_*D_,
            w2T[0] + (size_t)l*D_*FF_, w2T[1] + (size_t)l*D_*FF_, FF_, D_);
    }

    const int M = B_ * S_;
    for (int l = 0; l < L_; l++) {
        const float* curF = (l == 0) ? x : r2;

        // QKV = x @ Wqkv -> split bf16
        gemm_mma<128,2><<<dim3(3*D_/128, M/128, 1), 256, SMB128>>>(
            M, 3*D_, D_, xh, xl, D_, 0,
            wqT[0] + (size_t)l*3*D_*D_, wqT[1] + (size_t)l*3*D_*D_, D_, 0,
            nullptr, qh, ql, 3*D_, 0, nullptr);

        // fused attention (QK^T -> softmax -> PV), mask-aware
        flash_attn<<<dim3(S_/128, B_*H_), 256, SMFL>>>(qh, ql, ah, al);

        // Y = attn @ Wo + bo
        gemm_mma<128,0><<<dim3(D_/128, M/128, 1), 256, SMB128>>>(
            M, D_, D_, ah, al, D_, 0,
            woT[0] + (size_t)l*D_*D_, woT[1] + (size_t)l*D_*D_, D_, 0,
            Yf, nullptr, nullptr, D_, 0, bo + (size_t)l*D_);

        add_ln<<<M, 128>>>(Yf, curF, g1 + (size_t)l*D_, be1 + (size_t)l*D_, r1, xh, xl);

        // H = relu(x @ W1 + bf1) -> split
        gemm_mma<128,3><<<dim3(FF_/128, M/128, 1), 256, SMB128>>>(
            M, FF_, D_, xh, xl, D_, 0,
            w1T[0] + (size_t)l*FF_*D_, w1T[1] + (size_t)l*FF_*D_, D_, 0,
            nullptr, hh, hl, FF_, 0, bf1 + (size_t)l*FF_);

        // Y = H @ W2 + bf2
        gemm_mma<128,0><<<dim3(D_/128, M/128, 1), 256, SMB128>>>(
            M, D_, FF_, hh, hl, FF_, 0,
            w2T[0] + (size_t)l*D_*FF_, w2T[1] + (size_t)l*D_*FF_, FF_, 0,
            Yf, nullptr, nullptr, D_, 0, bf2 + (size_t)l*D_);

        float* dst = (l == L_ - 1) ? out : r2;
        add_ln<<<M, 128>>>(Yf, r1, g2 + (size_t)l*D_, be2 + (size_t)l*D_, dst, xh, xl);
    }
    (void)in_sizes; (void)n_in; (void)out_size;
}

// round 7
// speedup vs baseline: 3.4492x; 1.1059x over previous
#include <cuda_runtime.h>
#include <cuda_bf16.h>
#include <cstdint>
#include <cstddef>

#define B_  2
#define S_  2048
#define D_  512
#define H_  8
#define HD_ 64
#define FF_ 2048
#define L_  2
#define EPS_ 1e-5f

typedef __nv_bfloat16 bf16;

// ===================== PTX helpers (non-'a' gated only) =====================
__device__ __forceinline__ uint32_t smem_u32(const void* p) {
    uint32_t a;
    asm("{ .reg .u64 t; cvta.to.shared.u64 t, %1; cvt.u32.u64 %0, t; }" : "=r"(a) : "l"(p));
    return a;
}
__device__ __forceinline__ void cp16(uint32_t dst, const void* src) {
    asm volatile("cp.async.cg.shared.global [%0], [%1], 16;" :: "r"(dst), "l"(src));
}
#define CPC  asm volatile("cp.async.commit_group;" ::: "memory")
#define CPW1 asm volatile("cp.async.wait_group 1;" ::: "memory")
#define CPW0 asm volatile("cp.async.wait_group 0;" ::: "memory")
#define LDSM4(r0, r1, r2, r3, a) \
    asm volatile("ldmatrix.sync.aligned.m8n8.x4.shared.b16 {%0,%1,%2,%3}, [%4];" \
                 : "=r"(r0), "=r"(r1), "=r"(r2), "=r"(r3) : "r"(a))
#define LDSM4T(r0, r1, r2, r3, a) \
    asm volatile("ldmatrix.sync.aligned.m8n8.x4.trans.shared.b16 {%0,%1,%2,%3}, [%4];" \
                 : "=r"(r0), "=r"(r1), "=r"(r2), "=r"(r3) : "r"(a))

__device__ __forceinline__ void mma16816(float* c, const uint32_t* a, const uint32_t* b) {
    asm volatile("mma.sync.aligned.m16n8k16.row.col.f32.bf16.bf16.f32 "
                 "{%0,%1,%2,%3}, {%4,%5,%6,%7}, {%8,%9}, {%0,%1,%2,%3};"
                 : "+f"(c[0]), "+f"(c[1]), "+f"(c[2]), "+f"(c[3])
                 : "r"(a[0]), "r"(a[1]), "r"(a[2]), "r"(a[3]), "r"(b[0]), "r"(b[1]));
}

__device__ __forceinline__ uint32_t packbf(float a, float b) {
    __nv_bfloat162 t = __floats2bfloat162_rn(a, b);
    return *(uint32_t*)&t;
}

// ===================== device scratch =======================================
__device__ int  g_len[B_];
__device__ bf16 g_xh[B_*S_*D_],  g_xl[B_*S_*D_];
__device__ bf16 g_qh[B_*S_*3*D_], g_ql[B_*S_*3*D_];
__device__ bf16 g_ah[B_*S_*D_], g_al[B_*S_*D_];
__device__ float g_Yf[B_*S_*D_], g_r1[B_*S_*D_], g_r2[B_*S_*D_];
__device__ bf16 g_hh[B_*S_*FF_], g_hl[B_*S_*FF_];
__device__ bf16 g_wqT[2][L_*3*D_*D_];
__device__ bf16 g_woT[2][L_*D_*D_];
__device__ bf16 g_w1T[2][L_*FF_*D_];
__device__ bf16 g_w2T[2][L_*D_*FF_];

__device__ __forceinline__ void split_store(float v, bf16* H, bf16* L, size_t i) {
    bf16 h = __float2bfloat16(v);
    H[i] = h;
    L[i] = __float2bfloat16(v - __bfloat162float(h));
}

// ===================== mask prep (validated R1) =============================
__global__ void prep_mask(const unsigned char* __restrict__ m8) {
    __shared__ int s_cnt, s_bad;
    const int* m32 = (const int*)m8;
    for (int b = 0; b < B_; b++) {
        if (threadIdx.x == 0) { s_cnt = 0; s_bad = 0; }
        __syncthreads();
        int local = 0;
        for (int j = threadIdx.x; j < S_; j += blockDim.x)
            local += (m8[b * S_ + j] != 0) ? 1 : 0;
        atomicAdd(&s_cnt, local);
        __syncthreads();
        int c = s_cnt, bad = 0;
        for (int j = threadIdx.x; j < S_; j += blockDim.x) {
            int v = (m8[b * S_ + j] != 0) ? 1 : 0;
            if (v != ((j < c) ? 1 : 0)) bad = 1;
        }
        if (bad) atomicOr(&s_bad, 1);
        __syncthreads();
        if (s_bad != 0 || c < S_ / 2) {
            if (threadIdx.x == 0) s_cnt = 0;
            __syncthreads();
            local = 0;
            for (int j = threadIdx.x; j < S_; j += blockDim.x)
                local += (m32[b * S_ + j] != 0) ? 1 : 0;
            atomicAdd(&s_cnt, local);
            __syncthreads();
            c = s_cnt;
        }
        if (threadIdx.x == 0) g_len[b] = c;
        __syncthreads();
    }
}

// ===================== conversions ==========================================
__global__ void convert_split(const float* __restrict__ in, bf16* __restrict__ hi,
                              bf16* __restrict__ lo, int n) {
    int i = blockIdx.x * blockDim.x + threadIdx.x;
    if (i < n) split_store(in[i], hi, lo, i);
}

// W[K,N] fp32 -> T[N,K] split bf16
__global__ void transpose_split(const float* __restrict__ W, bf16* __restrict__ Th,
                                bf16* __restrict__ Tl, int K, int N) {
    __shared__ float t[32][33];
    int n0 = blockIdx.x * 32, k0 = blockIdx.y * 32;
    int tx = threadIdx.x, ty = threadIdx.y;       // (32, 8)
    #pragma unroll
    for (int i = 0; i < 4; i++)
        t[ty + 8*i][tx] = W[(size_t)(k0 + ty + 8*i) * N + n0 + tx];
    __syncthreads();
    #pragma unroll
    for (int i = 0; i < 4; i++)
        split_store(t[tx][ty + 8*i], Th, Tl, (size_t)(n0 + ty + 8*i) * K + k0 + tx);
}

// ===================== mma.sync GEMM (3-stage, single-sync) =================
// EPI: 0 fp32 (+bias), 2 split-bf16 out, 3 bias+relu -> split-bf16 out
template<int BN, int EPI>
__global__ __launch_bounds__(256, 1)
void gemm_mma(int M, int N, int K,
              const bf16* __restrict__ Ah_, const bf16* __restrict__ Al_, int lda, size_t sA,
              const bf16* __restrict__ Bh_, const bf16* __restrict__ Bl_, int ldb, size_t sB,
              float* __restrict__ Cf, bf16* __restrict__ Ch, bf16* __restrict__ Cl,
              int ldc, size_t sC, const float* __restrict__ bias)
{
    constexpr int WARPS_N = (BN == 128) ? 4 : 2;
    constexpr int WARPS_M = 8 / WARPS_N;
    constexpr int WM = 128 / WARPS_M;
    constexpr int WN = BN / WARPS_N;
    constexpr int MI = WM / 16;
    constexpr int NI = WN / 8;
    constexpr int STR = 40;
    constexpr int OFF_AL = 128 * STR;
    constexpr int OFF_BH = 256 * STR;
    constexpr int STG = (256 + 2 * BN) * STR;

    extern __shared__ __align__(16) bf16 sm[];

    const int z  = blockIdx.z;
    const int bm = blockIdx.y * 128;
    const int bn = blockIdx.x * BN;
    const int tid = threadIdx.x;
    const int wid = tid >> 5, lane = tid & 31;
    const int wm = wid / WARPS_N, wn = wid % WARPS_N;

    const int KP = K / 32;

    const bf16* pAh = Ah_ + (size_t)z * sA + (size_t)bm * lda;
    const bf16* pAl = Al_ + (size_t)z * sA + (size_t)bm * lda;
    const bf16* pBh = Bh_ + (size_t)z * sB + (size_t)bn * ldb;
    const bf16* pBl = Bl_ + (size_t)z * sB + (size_t)bn * ldb;
    const uint32_t smb = smem_u32(sm);

    auto load_stage = [&](int p, int st) {
        const size_t k0 = (size_t)p * 32;
        const uint32_t sb = smb + (uint32_t)st * STG * 2;
        for (int i = tid; i < 128 * 4; i += 256) {
            int r = i >> 2, ch = i & 3;
            uint32_t d = sb + (uint32_t)(r * STR + ch * 8) * 2;
            cp16(d,               pAh + (size_t)r * lda + k0 + ch * 8);
            cp16(d + OFF_AL * 2,  pAl + (size_t)r * lda + k0 + ch * 8);
        }
        for (int i = tid; i < BN * 4; i += 256) {
            int r = i >> 2, ch = i & 3;
            uint32_t d = sb + (uint32_t)(OFF_BH + r * STR + ch * 8) * 2;
            cp16(d,                pBh + (size_t)r * ldb + k0 + ch * 8);
            cp16(d + BN * STR * 2, pBl + (size_t)r * ldb + k0 + ch * 8);
        }
    };

    float c[MI][NI][4];
    #pragma unroll
    for (int i = 0; i < MI; i++)
        #pragma unroll
        for (int j = 0; j < NI; j++)
            #pragma unroll
            for (int q = 0; q < 4; q++) c[i][j][q] = 0.0f;

    load_stage(0, 0); CPC;
    if (KP > 1) load_stage(1, 1);
    CPC;

    int st = 0;
    for (int p = 0; p < KP; p++) {
        if (p < KP - 1) { CPW1; } else { CPW0; }
        __syncthreads();
        // stage (p-1)%3 is now free for all warps — prefetch p+2 into it
        if (p + 2 < KP) { load_stage(p + 2, (st + 2) % 3); }
        CPC;
        const uint32_t sb = smb + (uint32_t)st * STG * 2;

        #pragma unroll
        for (int ks = 0; ks < 2; ks++) {
            const int colo = ks * 16 + (lane >> 4) * 8;
            uint32_t aH[MI][4], aL[MI][4], bH[NI][2], bL[NI][2];
            #pragma unroll
            for (int mi = 0; mi < MI; mi++) {
                int row = wm * WM + mi * 16 + (lane & 15);
                uint32_t ad = sb + (uint32_t)(row * STR + colo) * 2;
                LDSM4(aH[mi][0], aH[mi][1], aH[mi][2], aH[mi][3], ad);
                LDSM4(aL[mi][0], aL[mi][1], aL[mi][2], aL[mi][3], ad + OFF_AL * 2);
            }
            #pragma unroll
            for (int j2 = 0; j2 < NI / 2; j2++) {
                int rowb = wn * WN + j2 * 16 + (lane & 15);
                uint32_t bd = sb + (uint32_t)(OFF_BH + rowb * STR + colo) * 2;
                uint32_t r0, r1, r2, r3;
                LDSM4(r0, r1, r2, r3, bd);
                bH[2*j2][0] = r0; bH[2*j2][1] = r2;
                bH[2*j2+1][0] = r1; bH[2*j2+1][1] = r3;
                LDSM4(r0, r1, r2, r3, bd + BN * STR * 2);
                bL[2*j2][0] = r0; bL[2*j2][1] = r2;
                bL[2*j2+1][0] = r1; bL[2*j2+1][1] = r3;
            }
            #pragma unroll
            for (int mi = 0; mi < MI; mi++)
                #pragma unroll
                for (int nj = 0; nj < NI; nj++) {
                    mma16816(c[mi][nj], aH[mi], bH[nj]);
                    mma16816(c[mi][nj], aH[mi], bL[nj]);
                    mma16816(c[mi][nj], aL[mi], bH[nj]);
                }
        }
        st = (st + 1) % 3;
    }

    #pragma unroll
    for (int mi = 0; mi < MI; mi++) {
        const int row = bm + wm * WM + mi * 16 + (lane >> 2);
        #pragma unroll
        for (int nj = 0; nj < NI; nj++) {
            const int col = bn + wn * WN + nj * 8 + 2 * (lane & 3);
            const size_t i0 = (size_t)z * sC + (size_t)row * ldc + col;
            const size_t i1 = i0 + (size_t)8 * ldc;
            float v0 = c[mi][nj][0], v1 = c[mi][nj][1];
            float v2 = c[mi][nj][2], v3 = c[mi][nj][3];
            if (EPI == 0) {
                if (bias) { v0 += bias[col]; v1 += bias[col + 1]; v2 += bias[col]; v3 += bias[col + 1]; }
                *(float2*)(Cf + i0) = make_float2(v0, v1);
                *(float2*)(Cf + i1) = make_float2(v2, v3);
            } else {
                if (EPI == 3) {
                    v0 = fmaxf(v0 + bias[col], 0.0f); v1 = fmaxf(v1 + bias[col + 1], 0.0f);
                    v2 = fmaxf(v2 + bias[col], 0.0f); v3 = fmaxf(v3 + bias[col + 1], 0.0f);
                }
                float h0 = __bfloat162float(__float2bfloat16(v0));
                float h1 = __bfloat162float(__float2bfloat16(v1));
                float h2 = __bfloat162float(__float2bfloat16(v2));
                float h3 = __bfloat162float(__float2bfloat16(v3));
                *(uint32_t*)(Ch + i0) = packbf(v0, v1);
                *(uint32_t*)(Cl + i0) = packbf(v0 - h0, v1 - h1);
                *(uint32_t*)(Ch + i1) = packbf(v2, v3);
                *(uint32_t*)(Cl + i1) = packbf(v2 - h2, v3 - h3);
            }
        }
    }
}

// ===================== fused flash attention ================================
// grid (S/128, B*H), 256 threads (8 warps, 16 q-rows each).
__global__ __launch_bounds__(256, 1)
void flash_attn(const bf16* __restrict__ qh, const bf16* __restrict__ ql,
                bf16* __restrict__ ah, bf16* __restrict__ al)
{
    constexpr int STR = 72;
    constexpr int PANEL = 128 * STR;
    extern __shared__ __align__(16) bf16 sm[];

    const int z   = blockIdx.y;
    const int qt  = blockIdx.x * 128;
    const int len = g_len[z / H_];
    const int tid = threadIdx.x, wid = tid >> 5, lane = tid & 31;

    // ---- fully-masked q tile: emit zeros and exit ----
    if (qt >= len) {
        uint4 zz = make_uint4(0, 0, 0, 0);
        const size_t ob = (size_t)z * S_ * HD_ + (size_t)qt * HD_;
        for (int i = tid; i < 128 * HD_ / 8; i += 256) {
            *(uint4*)(ah + ob + (size_t)i * 8) = zz;
            *(uint4*)(al + ob + (size_t)i * 8) = zz;
        }
        return;
    }

    const int nkt = (len + 127) >> 7;
    const uint32_t smb = smem_u32(sm);
    const size_t hbase = (size_t)z * S_ * 192;

    for (int i = tid; i < 128 * 8; i += 256) {
        int r = i >> 3, ch = i & 7;
        uint32_t d = smb + (uint32_t)(r * STR + ch * 8) * 2;
        const size_t g = hbase + (size_t)(qt + r) * 192 + ch * 8;
        cp16(d, qh + g);
        cp16(d + PANEL * 2, ql + g);
    }
    auto load_kv = [&](int j, int st) {
        const uint32_t sb = smb + (uint32_t)(2 * PANEL + st * 4 * PANEL) * 2;
        for (int i = tid; i < 128 * 8; i += 256) {
            int r = i >> 3, ch = i & 7;
            uint32_t d = sb + (uint32_t)(r * STR + ch * 8) * 2;
            const size_t g = hbase + (size_t)(j * 128 + r) * 192 + ch * 8;
            cp16(d,                 qh + g + 64);
            cp16(d + PANEL * 2,     ql + g + 64);
            cp16(d + 2 * PANEL * 2, qh + g + 128);
            cp16(d + 3 * PANEL * 2, ql + g + 128);
        }
    };
    load_kv(0, 0); CPC;
    if (nkt > 1) load_kv(1, 1);
    CPC;
    CPW1; __syncthreads();

    uint32_t qH[4][4], qL[4][4];
    {
        int row = wid * 16 + (lane & 15);
        #pragma unroll
        for (int kc = 0; kc < 4; kc++) {
            uint32_t a = smb + (uint32_t)(row * STR + kc * 16 + ((lane >> 4) << 3)) * 2;
            LDSM4(qH[kc][0], qH[kc][1], qH[kc][2], qH[kc][3], a);
            LDSM4(qL[kc][0], qL[kc][1], qL[kc][2], qL[kc][3], a + PANEL * 2);
        }
    }

    float m0 = -1e30f, m1 = -1e30f, l0 = 0.0f, l1 = 0.0f;
    float o[8][4];
    #pragma unroll
    for (int t = 0; t < 8; t++)
        #pragma unroll
        for (int q = 0; q < 4; q++) o[t][q] = 0.0f;

    for (int j = 0; j < nkt; j++) {
        if (j > 0) {
            if (j + 1 < nkt) { CPW1; } else { CPW0; }
            __syncthreads();
        }
        const int st = j & 1;
        const uint32_t kb = smb + (uint32_t)(2 * PANEL + st * 4 * PANEL) * 2;

        float s[16][4];
        #pragma unroll
        for (int t = 0; t < 16; t++)
            #pragma unroll
            for (int q = 0; q < 4; q++) s[t][q] = 0.0f;

        #pragma unroll
        for (int kc = 0; kc < 4; kc++) {
            #pragma unroll
            for (int g = 0; g < 8; g++) {
                int rowb = g * 16 + (lane & 15);
                uint32_t ad = kb + (uint32_t)(rowb * STR + kc * 16 + ((lane >> 4) << 3)) * 2;
                uint32_t h0, h1, h2, h3, e0, e1, e2, e3;
                LDSM4(h0, h1, h2, h3, ad);
                LDSM4(e0, e1, e2, e3, ad + PANEL * 2);
                uint32_t bh0[2] = {h0, h2}, bh1[2] = {h1, h3};
                uint32_t bl0[2] = {e0, e2}, bl1[2] = {e1, e3};
                mma16816(s[2*g],     qH[kc], bh0);
                mma16816(s[2*g],     qH[kc], bl0);
                mma16816(s[2*g],     qL[kc], bh0);
                mma16816(s[2*g+1],   qH[kc], bh1);
                mma16816(s[2*g+1],   qH[kc], bl1);
                mma16816(s[2*g+1],   qL[kc], bh1);
            }
        }

        #pragma unroll
        for (int t = 0; t < 16; t++)
            #pragma unroll
            for (int q = 0; q < 4; q++) s[t][q] *= 0.125f;
        if ((j == nkt - 1) && (len & 127)) {
            #pragma unroll
            for (int t = 0; t < 16; t++) {
                int col = j * 128 + t * 8 + 2 * (lane & 3);
                if (col     >= len) { s[t][0] = -1e9f; s[t][2] = -1e9f; }
                if (col + 1 >= len) { s[t][1] = -1e9f; s[t][3] = -1e9f; }
            }
        }

        float mx0 = -1e30f, mx1 = -1e30f;
        #pragma unroll
        for (int t = 0; t < 16; t++) {
            mx0 = fmaxf(mx0, fmaxf(s[t][0], s[t][1]));
            mx1 = fmaxf(mx1, fmaxf(s[t][2], s[t][3]));
        }
        mx0 = fmaxf(mx0, __shfl_xor_sync(0xffffffffu, mx0, 1));
        mx0 = fmaxf(mx0, __shfl_xor_sync(0xffffffffu, mx0, 2));
        mx1 = fmaxf(mx1, __shfl_xor_sync(0xffffffffu, mx1, 1));
        mx1 = fmaxf(mx1, __shfl_xor_sync(0xffffffffu, mx1, 2));
        float mn0 = fmaxf(m0, mx0), mn1 = fmaxf(m1, mx1);
        float sc0 = __expf(m0 - mn0), sc1 = __expf(m1 - mn1);
        m0 = mn0; m1 = mn1;
        float sum0 = 0.0f, sum1 = 0.0f;
        #pragma unroll
        for (int t = 0; t < 16; t++) {
            s[t][0] = __expf(s[t][0] - mn0); sum0 += s[t][0];
            s[t][1] = __expf(s[t][1] - mn0); sum0 += s[t][1];
            s[t][2] = __expf(s[t][2] - mn1); sum1 += s[t][2];
            s[t][3] = __expf(s[t][3] - mn1); sum1 += s[t][3];
        }
        sum0 += __shfl_xor_sync(0xffffffffu, sum0, 1);
        sum0 += __shfl_xor_sync(0xffffffffu, sum0, 2);
        sum1 += __shfl_xor_sync(0xffffffffu, sum1, 1);
        sum1 += __shfl_xor_sync(0xffffffffu, sum1, 2);
        l0 = l0 * sc0 + sum0;
        l1 = l1 * sc1 + sum1;
        #pragma unroll
        for (int t = 0; t < 8; t++) {
            o[t][0] *= sc0; o[t][1] *= sc0;
            o[t][2] *= sc1; o[t][3] *= sc1;
        }

        #pragma unroll
        for (int kc = 0; kc < 8; kc++) {
            uint32_t pH[4], pL[4];
            {
                float a0 = s[2*kc][0],   a1 = s[2*kc][1];
                float a2 = s[2*kc][2],   a3 = s[2*kc][3];
                float b0 = s[2*kc+1][0], b1 = s[2*kc+1][1];
                float b2 = s[2*kc+1][2], b3 = s[2*kc+1][3];
                pH[0] = packbf(a0, a1); pH[1] = packbf(a2, a3);
                pH[2] = packbf(b0, b1); pH[3] = packbf(b2, b3);
                float ra0 = a0 - __bfloat162float(__float2bfloat16(a0));
                float ra1 = a1 - __bfloat162float(__float2bfloat16(a1));
                float ra2 = a2 - __bfloat162float(__float2bfloat16(a2));
                float ra3 = a3 - __bfloat162float(__float2bfloat16(a3));
                float rb0 = b0 - __bfloat162float(__float2bfloat16(b0));
                float rb1 = b1 - __bfloat162float(__float2bfloat16(b1));
                float rb2 = b2 - __bfloat162float(__float2bfloat16(b2));
                float rb3 = b3 - __bfloat162float(__float2bfloat16(b3));
                pL[0] = packbf(ra0, ra1); pL[1] = packbf(ra2, ra3);
                pL[2] = packbf(rb0, rb1); pL[3] = packbf(rb2, rb3);
            }
            #pragma unroll
            for (int g = 0; g < 4; g++) {
                int krow = kc * 16 + ((lane >> 3) & 1) * 8 + (lane & 7);
                int ncol = g * 16 + ((lane >> 4) << 3);
                uint32_t ad = kb + (uint32_t)(2 * PANEL + krow * STR + ncol) * 2;
                uint32_t h0, h1, h2, h3, e0, e1, e2, e3;
                LDSM4T(h0, h1, h2, h3, ad);
                LDSM4T(e0, e1, e2, e3, ad + PANEL * 2);
                uint32_t vh0[2] = {h0, h1}, vh1[2] = {h2, h3};
                uint32_t vl0[2] = {e0, e1}, vl1[2] = {e2, e3};
                mma16816(o[2*g],   pH, vh0);
                mma16816(o[2*g],   pH, vl0);
                mma16816(o[2*g],   pL, vh0);
                mma16816(o[2*g+1], pH, vh1);
                mma16816(o[2*g+1], pH, vl1);
                mma16816(o[2*g+1], pL, vh1);
            }
        }
        __syncthreads();
        if (j + 2 < nkt) load_kv(j + 2, st);
        CPC;
    }

    const int q0 = qt + wid * 16 + (lane >> 2);
    const int q1 = q0 + 8;
    const float inv0 = (q0 < len) ? (1.0f / l0) : 0.0f;
    const float inv1 = (q1 < len) ? (1.0f / l1) : 0.0f;
    const size_t b0 = (size_t)z * S_ * HD_ + (size_t)q0 * HD_;
    const size_t b1 = (size_t)z * S_ * HD_ + (size_t)q1 * HD_;
    #pragma unroll
    for (int t = 0; t < 8; t++) {
        int col = t * 8 + 2 * (lane & 3);
        float v0 = o[t][0] * inv0, v1 = o[t][1] * inv0;
        float v2 = o[t][2] * inv1, v3 = o[t][3] * inv1;
        float h0 = __bfloat162float(__float2bfloat16(v0));
        float h1 = __bfloat162float(__float2bfloat16(v1));
        float h2 = __bfloat162float(__float2bfloat16(v2));
        float h3 = __bfloat162float(__float2bfloat16(v3));
        *(uint32_t*)(ah + b0 + col) = packbf(v0, v1);
        *(uint32_t*)(al + b0 + col) = packbf(v0 - h0, v1 - h1);
        *(uint32_t*)(ah + b1 + col) = packbf(v2, v3);
        *(uint32_t*)(al + b1 + col) = packbf(v2 - h2, v3 - h3);
    }
}

// ===================== layernorm ============================================
__device__ __forceinline__ float warpSum(float v) {
    #pragma unroll
    for (int o = 16; o > 0; o >>= 1) v += __shfl_xor_sync(0xffffffffu, v, o);
    return v;
}

__global__ void add_ln(const float* __restrict__ Y, const float* __restrict__ R,
                       const float* __restrict__ g, const float* __restrict__ be,
                       float* __restrict__ outF, bf16* __restrict__ outH,
                       bf16* __restrict__ outL)
{
    const int r = blockIdx.x;
    const float* y = Y + (size_t)r * D_;
    const float* x = R + (size_t)r * D_;
    const int t = threadIdx.x;
    const int lane = t & 31, wid = t >> 5;
    __shared__ float sm1[4], sm2[4];
    float v[4], s = 0.0f;
    #pragma unroll
    for (int i = 0; i < 4; i++) { v[i] = y[t + 128*i] + x[t + 128*i]; s += v[i]; }
    float w = warpSum(s);
    if (lane == 0) sm1[wid] = w;
    __syncthreads();
    float mean = (sm1[0] + sm1[1] + sm1[2] + sm1[3]) * (1.0f / D_);
    float vs = 0.0f;
    #pragma unroll
    for (int i = 0; i < 4; i++) { float d = v[i] - mean; vs += d * d; }
    w = warpSum(vs);
    if (lane == 0) sm2[wid] = w;
    __syncthreads();
    float rstd = rsqrtf((sm2[0] + sm2[1] + sm2[2] + sm2[3]) * (1.0f / D_) + EPS_);
    #pragma unroll
    for (int i = 0; i < 4; i++) {
        int cc = t + 128 * i;
        float o = g[cc] * (v[i] - mean) * rstd + be[cc];
        size_t oi = (size_t)r * D_ + cc;
        outF[oi] = o;
        split_store(o, outH, outL, oi);
    }
}

// ===================== launch ===============================================
extern "C" void kernel_launch(void* const* d_in, const int* in_sizes, int n_in,
                              void* d_out, int out_size)
{
    const float* x    = (const float*)d_in[0];
    const unsigned char* mask = (const unsigned char*)d_in[1];
    const float* Wqkv = (const float*)d_in[2];
    const float* Wo   = (const float*)d_in[3];
    const float* bo   = (const float*)d_in[4];
    const float* g1   = (const float*)d_in[5];
    const float* be1  = (const float*)d_in[6];
    const float* W1   = (const float*)d_in[7];
    const float* bf1  = (const float*)d_in[8];
    const float* W2   = (const float*)d_in[9];
    const float* bf2  = (const float*)d_in[10];
    const float* g2   = (const float*)d_in[11];
    const float* be2  = (const float*)d_in[12];
    float* out = (float*)d_out;

    bf16 *xh, *xl, *qh, *ql, *ah, *al, *hh, *hl;
    float *Yf, *r1, *r2;
    bf16 *wqT[2], *woT[2], *w1T[2], *w2T[2];
    cudaGetSymbolAddress((void**)&xh, g_xh);   cudaGetSymbolAddress((void**)&xl, g_xl);
    cudaGetSymbolAddress((void**)&qh, g_qh);   cudaGetSymbolAddress((void**)&ql, g_ql);
    cudaGetSymbolAddress((void**)&ah, g_ah);   cudaGetSymbolAddress((void**)&al, g_al);
    cudaGetSymbolAddress((void**)&Yf, g_Yf);
    cudaGetSymbolAddress((void**)&r1, g_r1);   cudaGetSymbolAddress((void**)&r2, g_r2);
    cudaGetSymbolAddress((void**)&hh, g_hh);   cudaGetSymbolAddress((void**)&hl, g_hl);
    cudaGetSymbolAddress((void**)&wqT[0], g_wqT); cudaGetSymbolAddress((void**)&woT[0], g_woT);
    cudaGetSymbolAddress((void**)&w1T[0], g_w1T); cudaGetSymbolAddress((void**)&w2T[0], g_w2T);
    wqT[1] = wqT[0] + L_*3*D_*D_; woT[1] = woT[0] + L_*D_*D_;
    w1T[1] = w1T[0] + L_*FF_*D_;  w2T[1] = w2T[0] + L_*D_*FF_;

    const int SMB128 = 3 * (256 + 256) * 40 * 2;   // 122880 (3 stages)
    const int SMFL   = 10 * 128 * 72 * 2;          // 184320
    cudaFuncSetAttribute(gemm_mma<128,0>, cudaFuncAttributeMaxDynamicSharedMemorySize, SMB128);
    cudaFuncSetAttribute(gemm_mma<128,2>, cudaFuncAttributeMaxDynamicSharedMemorySize, SMB128);
    cudaFuncSetAttribute(gemm_mma<128,3>, cudaFuncAttributeMaxDynamicSharedMemorySize, SMB128);
    cudaFuncSetAttribute(flash_attn,      cudaFuncAttributeMaxDynamicSharedMemorySize, SMFL);

    prep_mask<<<1, 256>>>(mask);
    convert_split<<<(B_*S_*D_ + 255)/256, 256>>>(x, xh, xl, B_*S_*D_);

    dim3 tb(32, 8);
    for (int l = 0; l < L_; l++) {
        transpose_split<<<dim3(3*D_/32, D_/32), tb>>>(Wqkv + (size_t)l*D_*3*D_,
            wqT[0] + (size_t)l*3*D_*D_, wqT[1] + (size_t)l*3*D_*D_, D_, 3*D_);
        transpose_split<<<dim3(D_/32, D_/32), tb>>>(Wo + (size_t)l*D_*D_,
            woT[0] + (size_t)l*D_*D_, woT[1] + (size_t)l*D_*D_, D_, D_);
        transpose_split<<<dim3(FF_/32, D_/32), tb>>>(W1 + (size_t)l*D_*FF_,
            w1T[0] + (size_t)l*FF_*D_, w1T[1] + (size_t)l*FF_*D_, D_, FF_);
        transpose_split<<<dim3(D_/32, FF_/32), tb>>>(W2 + (size_t)l*FF_*D_,
            w2T[0] + (size_t)l*D_*FF_, w2T[1] + (size_t)l*D_*FF_, FF_, D_);
    }

    const int M = B_ * S_;
    for (int l = 0; l < L_; l++) {
        const float* curF = (l == 0) ? x : r2;

        gemm_mma<128,2><<<dim3(3*D_/128, M/128, 1), 256, SMB128>>>(
            M, 3*D_, D_, xh, xl, D_, 0,
            wqT[0] + (size_t)l*3*D_*D_, wqT[1] + (size_t)l*3*D_*D_, D_, 0,
            nullptr, qh, ql, 3*D_, 0, nullptr);

        flash_attn<<<dim3(S_/128, B_*H_), 256, SMFL>>>(qh, ql, ah, al);

        gemm_mma<128,0><<<dim3(D_/128, M/128, 1), 256, SMB128>>>(
            M, D_, D_, ah, al, D_, 0,
            woT[0] + (size_t)l*D_*D_, woT[1] + (size_t)l*D_*D_, D_, 0,
            Yf, nullptr, nullptr, D_, 0, bo + (size_t)l*D_);

        add_ln<<<M, 128>>>(Yf, curF, g1 + (size_t)l*D_, be1 + (size_t)l*D_, r1, xh, xl);

        gemm_mma<128,3><<<dim3(FF_/128, M/128, 1), 256, SMB128>>>(
            M, FF_, D_, xh, xl, D_, 0,
            w1T[0] + (size_t)l*FF_*D_, w1T[1] + (size_t)l*FF_*D_, D_, 0,
            nullptr, hh, hl, FF_, 0, bf1 + (size_t)l*FF_);

        gemm_mma<128,0><<<dim3(D_/128, M/128, 1), 256, SMB128>>>(
            M, D_, FF_, hh, hl, FF_, 0,
            w2T[0] + (size_t)l*D_*FF_, w2T[1] + (size_t)l*D_*FF_, FF_, 0,
            Yf, nullptr, nullptr, D_, 0, bf2 + (size_t)l*D_);

        float* dst = (l == L_ - 1) ? out : r2;
        add_ln<<<M, 128>>>(Yf, r1, g2 + (size_t)l*D_, be2 + (size_t)l*D_, dst, xh, xl);
    }
    (void)in_sizes; (void)n_in; (void)out_size;
}

// round 8
// speedup vs baseline: 3.6365x; 1.0543x over previous
#include <cuda_runtime.h>
#include <cuda_bf16.h>
#include <cstdint>
#include <cstddef>

#define B_  2
#define S_  2048
#define D_  512
#define H_  8
#define HD_ 64
#define FF_ 2048
#define L_  2
#define EPS_ 1e-5f

typedef __nv_bfloat16 bf16;

// ===================== PTX helpers (non-'a' gated only) =====================
__device__ __forceinline__ uint32_t smem_u32(const void* p) {
    uint32_t a;
    asm("{ .reg .u64 t; cvta.to.shared.u64 t, %1; cvt.u32.u64 %0, t; }" : "=r"(a) : "l"(p));
    return a;
}
__device__ __forceinline__ void cp16(uint32_t dst, const void* src) {
    asm volatile("cp.async.cg.shared.global [%0], [%1], 16;" :: "r"(dst), "l"(src));
}
#define CPC  asm volatile("cp.async.commit_group;" ::: "memory")
#define CPW1 asm volatile("cp.async.wait_group 1;" ::: "memory")
#define CPW0 asm volatile("cp.async.wait_group 0;" ::: "memory")
#define LDSM4(r0, r1, r2, r3, a) \
    asm volatile("ldmatrix.sync.aligned.m8n8.x4.shared.b16 {%0,%1,%2,%3}, [%4];" \
                 : "=r"(r0), "=r"(r1), "=r"(r2), "=r"(r3) : "r"(a))
#define LDSM4T(r0, r1, r2, r3, a) \
    asm volatile("ldmatrix.sync.aligned.m8n8.x4.trans.shared.b16 {%0,%1,%2,%3}, [%4];" \
                 : "=r"(r0), "=r"(r1), "=r"(r2), "=r"(r3) : "r"(a))

__device__ __forceinline__ void mma16816(float* c, const uint32_t* a, const uint32_t* b) {
    asm volatile("mma.sync.aligned.m16n8k16.row.col.f32.bf16.bf16.f32 "
                 "{%0,%1,%2,%3}, {%4,%5,%6,%7}, {%8,%9}, {%0,%1,%2,%3};"
                 : "+f"(c[0]), "+f"(c[1]), "+f"(c[2]), "+f"(c[3])
                 : "r"(a[0]), "r"(a[1]), "r"(a[2]), "r"(a[3]), "r"(b[0]), "r"(b[1]));
}

__device__ __forceinline__ uint32_t packbf(float a, float b) {
    __nv_bfloat162 t = __floats2bfloat162_rn(a, b);
    return *(uint32_t*)&t;
}

// ===================== device scratch =======================================
__device__ int  g_len[B_];
__device__ bf16 g_xh[B_*S_*D_],  g_xl[B_*S_*D_];
__device__ bf16 g_qh[B_*S_*3*D_], g_ql[B_*S_*3*D_];
__device__ bf16 g_ah[B_*S_*D_], g_al[B_*S_*D_];
__device__ float g_Yf[B_*S_*D_], g_r1[B_*S_*D_], g_r2[B_*S_*D_];
__device__ bf16 g_hh[B_*S_*FF_], g_hl[B_*S_*FF_];
__device__ bf16 g_wqT[2][L_*3*D_*D_];
__device__ bf16 g_woT[2][L_*D_*D_];
__device__ bf16 g_w1T[2][L_*FF_*D_];
__device__ bf16 g_w2T[2][L_*D_*FF_];

__device__ __forceinline__ void split_store(float v, bf16* H, bf16* L, size_t i) {
    bf16 h = __float2bfloat16(v);
    H[i] = h;
    L[i] = __float2bfloat16(v - __bfloat162float(h));
}

// ===================== mask prep (validated R1) =============================
__global__ void prep_mask(const unsigned char* __restrict__ m8) {
    __shared__ int s_cnt, s_bad;
    const int* m32 = (const int*)m8;
    for (int b = 0; b < B_; b++) {
        if (threadIdx.x == 0) { s_cnt = 0; s_bad = 0; }
        __syncthreads();
        int local = 0;
        for (int j = threadIdx.x; j < S_; j += blockDim.x)
            local += (m8[b * S_ + j] != 0) ? 1 : 0;
        atomicAdd(&s_cnt, local);
        __syncthreads();
        int c = s_cnt, bad = 0;
        for (int j = threadIdx.x; j < S_; j += blockDim.x) {
            int v = (m8[b * S_ + j] != 0) ? 1 : 0;
            if (v != ((j < c) ? 1 : 0)) bad = 1;
        }
        if (bad) atomicOr(&s_bad, 1);
        __syncthreads();
        if (s_bad != 0 || c < S_ / 2) {
            if (threadIdx.x == 0) s_cnt = 0;
            __syncthreads();
            local = 0;
            for (int j = threadIdx.x; j < S_; j += blockDim.x)
                local += (m32[b * S_ + j] != 0) ? 1 : 0;
            atomicAdd(&s_cnt, local);
            __syncthreads();
            c = s_cnt;
        }
        if (threadIdx.x == 0) g_len[b] = c;
        __syncthreads();
    }
}

// ===================== conversions ==========================================
__global__ void convert_split(const float* __restrict__ in, bf16* __restrict__ hi,
                              bf16* __restrict__ lo, int n) {
    int i = blockIdx.x * blockDim.x + threadIdx.x;
    if (i < n) split_store(in[i], hi, lo, i);
}

// W[K,N] fp32 -> T[N,K] split bf16
__global__ void transpose_split(const float* __restrict__ W, bf16* __restrict__ Th,
                                bf16* __restrict__ Tl, int K, int N) {
    __shared__ float t[32][33];
    int n0 = blockIdx.x * 32, k0 = blockIdx.y * 32;
    int tx = threadIdx.x, ty = threadIdx.y;       // (32, 8)
    #pragma unroll
    for (int i = 0; i < 4; i++)
        t[ty + 8*i][tx] = W[(size_t)(k0 + ty + 8*i) * N + n0 + tx];
    __syncthreads();
    #pragma unroll
    for (int i = 0; i < 4; i++)
        split_store(t[tx][ty + 8*i], Th, Tl, (size_t)(n0 + ty + 8*i) * K + k0 + tx);
}

// ===================== mma.sync GEMM (2-stage, 2 CTAs/SM) ===================
// EPI: 0 fp32 (+bias), 2 split-bf16 out, 3 bias+relu -> split-bf16 out
template<int BN, int EPI>
__global__ __launch_bounds__(256, 2)
void gemm_mma(int M, int N, int K,
              const bf16* __restrict__ Ah_, const bf16* __restrict__ Al_, int lda, size_t sA,
              const bf16* __restrict__ Bh_, const bf16* __restrict__ Bl_, int ldb, size_t sB,
              float* __restrict__ Cf, bf16* __restrict__ Ch, bf16* __restrict__ Cl,
              int ldc, size_t sC, const float* __restrict__ bias)
{
    constexpr int WARPS_N = (BN == 128) ? 4 : 2;
    constexpr int WARPS_M = 8 / WARPS_N;
    constexpr int WM = 128 / WARPS_M;
    constexpr int WN = BN / WARPS_N;
    constexpr int MI = WM / 16;
    constexpr int NI = WN / 8;
    constexpr int STR = 40;
    constexpr int OFF_AL = 128 * STR;
    constexpr int OFF_BH = 256 * STR;
    constexpr int STG = (256 + 2 * BN) * STR;

    extern __shared__ __align__(16) bf16 sm[];

    const int z  = blockIdx.z;
    const int bm = blockIdx.y * 128;
    const int bn = blockIdx.x * BN;
    const int tid = threadIdx.x;
    const int wid = tid >> 5, lane = tid & 31;
    const int wm = wid / WARPS_N, wn = wid % WARPS_N;

    const int KP = K / 32;

    const bf16* pAh = Ah_ + (size_t)z * sA + (size_t)bm * lda;
    const bf16* pAl = Al_ + (size_t)z * sA + (size_t)bm * lda;
    const bf16* pBh = Bh_ + (size_t)z * sB + (size_t)bn * ldb;
    const bf16* pBl = Bl_ + (size_t)z * sB + (size_t)bn * ldb;
    const uint32_t smb = smem_u32(sm);

    auto load_stage = [&](int p, int st) {
        const size_t k0 = (size_t)p * 32;
        const uint32_t sb = smb + (uint32_t)st * STG * 2;
        for (int i = tid; i < 128 * 4; i += 256) {
            int r = i >> 2, ch = i & 3;
            uint32_t d = sb + (uint32_t)(r * STR + ch * 8) * 2;
            cp16(d,               pAh + (size_t)r * lda + k0 + ch * 8);
            cp16(d + OFF_AL * 2,  pAl + (size_t)r * lda + k0 + ch * 8);
        }
        for (int i = tid; i < BN * 4; i += 256) {
            int r = i >> 2, ch = i & 3;
            uint32_t d = sb + (uint32_t)(OFF_BH + r * STR + ch * 8) * 2;
            cp16(d,                pBh + (size_t)r * ldb + k0 + ch * 8);
            cp16(d + BN * STR * 2, pBl + (size_t)r * ldb + k0 + ch * 8);
        }
    };

    float c[MI][NI][4];
    #pragma unroll
    for (int i = 0; i < MI; i++)
        #pragma unroll
        for (int j = 0; j < NI; j++)
            #pragma unroll
            for (int q = 0; q < 4; q++) c[i][j][q] = 0.0f;

    load_stage(0, 0); CPC;
    if (KP > 1) load_stage(1, 1);
    CPC;

    for (int p = 0; p < KP; p++) {
        if (p < KP - 1) { CPW1; } else { CPW0; }
        __syncthreads();
        const int st = p & 1;
        const uint32_t sb = smb + (uint32_t)st * STG * 2;

        #pragma unroll
        for (int ks = 0; ks < 2; ks++) {
            const int colo = ks * 16 + (lane >> 4) * 8;
            uint32_t aH[MI][4], aL[MI][4], bH[NI][2], bL[NI][2];
            #pragma unroll
            for (int mi = 0; mi < MI; mi++) {
                int row = wm * WM + mi * 16 + (lane & 15);
                uint32_t ad = sb + (uint32_t)(row * STR + colo) * 2;
                LDSM4(aH[mi][0], aH[mi][1], aH[mi][2], aH[mi][3], ad);
                LDSM4(aL[mi][0], aL[mi][1], aL[mi][2], aL[mi][3], ad + OFF_AL * 2);
            }
            #pragma unroll
            for (int j2 = 0; j2 < NI / 2; j2++) {
                int rowb = wn * WN + j2 * 16 + (lane & 15);
                uint32_t bd = sb + (uint32_t)(OFF_BH + rowb * STR + colo) * 2;
                uint32_t r0, r1, r2, r3;
                LDSM4(r0, r1, r2, r3, bd);
                bH[2*j2][0] = r0; bH[2*j2][1] = r2;
                bH[2*j2+1][0] = r1; bH[2*j2+1][1] = r3;
                LDSM4(r0, r1, r2, r3, bd + BN * STR * 2);
                bL[2*j2][0] = r0; bL[2*j2][1] = r2;
                bL[2*j2+1][0] = r1; bL[2*j2+1][1] = r3;
            }
            #pragma unroll
            for (int mi = 0; mi < MI; mi++)
                #pragma unroll
                for (int nj = 0; nj < NI; nj++) {
                    mma16816(c[mi][nj], aH[mi], bH[nj]);
                    mma16816(c[mi][nj], aH[mi], bL[nj]);
                    mma16816(c[mi][nj], aL[mi], bH[nj]);
                }
        }
        __syncthreads();
        if (p + 2 < KP) { load_stage(p + 2, st); }
        CPC;
    }

    #pragma unroll
    for (int mi = 0; mi < MI; mi++) {
        const int row = bm + wm * WM + mi * 16 + (lane >> 2);
        #pragma unroll
        for (int nj = 0; nj < NI; nj++) {
            const int col = bn + wn * WN + nj * 8 + 2 * (lane & 3);
            const size_t i0 = (size_t)z * sC + (size_t)row * ldc + col;
            const size_t i1 = i0 + (size_t)8 * ldc;
            float v0 = c[mi][nj][0], v1 = c[mi][nj][1];
            float v2 = c[mi][nj][2], v3 = c[mi][nj][3];
            if (EPI == 0) {
                if (bias) { v0 += bias[col]; v1 += bias[col + 1]; v2 += bias[col]; v3 += bias[col + 1]; }
                *(float2*)(Cf + i0) = make_float2(v0, v1);
                *(float2*)(Cf + i1) = make_float2(v2, v3);
            } else {
                if (EPI == 3) {
                    v0 = fmaxf(v0 + bias[col], 0.0f); v1 = fmaxf(v1 + bias[col + 1], 0.0f);
                    v2 = fmaxf(v2 + bias[col], 0.0f); v3 = fmaxf(v3 + bias[col + 1], 0.0f);
                }
                float h0 = __bfloat162float(__float2bfloat16(v0));
                float h1 = __bfloat162float(__float2bfloat16(v1));
                float h2 = __bfloat162float(__float2bfloat16(v2));
                float h3 = __bfloat162float(__float2bfloat16(v3));
                *(uint32_t*)(Ch + i0) = packbf(v0, v1);
                *(uint32_t*)(Cl + i0) = packbf(v0 - h0, v1 - h1);
                *(uint32_t*)(Ch + i1) = packbf(v2, v3);
                *(uint32_t*)(Cl + i1) = packbf(v2 - h2, v3 - h3);
            }
        }
    }
}

// ===================== fused flash attention ================================
// grid (S/128, B*H), 256 threads (8 warps, 16 q-rows each).
__global__ __launch_bounds__(256, 1)
void flash_attn(const bf16* __restrict__ qh, const bf16* __restrict__ ql,
                bf16* __restrict__ ah, bf16* __restrict__ al)
{
    constexpr int STR = 72;
    constexpr int PANEL = 128 * STR;
    extern __shared__ __align__(16) bf16 sm[];

    const int z   = blockIdx.y;
    const int qt  = blockIdx.x * 128;
    const int len = g_len[z / H_];
    const int tid = threadIdx.x, wid = tid >> 5, lane = tid & 31;

    if (qt >= len) {
        uint4 zz = make_uint4(0, 0, 0, 0);
        const size_t ob = (size_t)z * S_ * HD_ + (size_t)qt * HD_;
        for (int i = tid; i < 128 * HD_ / 8; i += 256) {
            *(uint4*)(ah + ob + (size_t)i * 8) = zz;
            *(uint4*)(al + ob + (size_t)i * 8) = zz;
        }
        return;
    }

    const int nkt = (len + 127) >> 7;
    const uint32_t smb = smem_u32(sm);
    const size_t hbase = (size_t)z * S_ * 192;

    for (int i = tid; i < 128 * 8; i += 256) {
        int r = i >> 3, ch = i & 7;
        uint32_t d = smb + (uint32_t)(r * STR + ch * 8) * 2;
        const size_t g = hbase + (size_t)(qt + r) * 192 + ch * 8;
        cp16(d, qh + g);
        cp16(d + PANEL * 2, ql + g);
    }
    auto load_kv = [&](int j, int st) {
        const uint32_t sb = smb + (uint32_t)(2 * PANEL + st * 4 * PANEL) * 2;
        for (int i = tid; i < 128 * 8; i += 256) {
            int r = i >> 3, ch = i & 7;
            uint32_t d = sb + (uint32_t)(r * STR + ch * 8) * 2;
            const size_t g = hbase + (size_t)(j * 128 + r) * 192 + ch * 8;
            cp16(d,                 qh + g + 64);
            cp16(d + PANEL * 2,     ql + g + 64);
            cp16(d + 2 * PANEL * 2, qh + g + 128);
            cp16(d + 3 * PANEL * 2, ql + g + 128);
        }
    };
    load_kv(0, 0); CPC;
    if (nkt > 1) load_kv(1, 1);
    CPC;
    CPW1; __syncthreads();

    uint32_t qH[4][4], qL[4][4];
    {
        int row = wid * 16 + (lane & 15);
        #pragma unroll
        for (int kc = 0; kc < 4; kc++) {
            uint32_t a = smb + (uint32_t)(row * STR + kc * 16 + ((lane >> 4) << 3)) * 2;
            LDSM4(qH[kc][0], qH[kc][1], qH[kc][2], qH[kc][3], a);
            LDSM4(qL[kc][0], qL[kc][1], qL[kc][2], qL[kc][3], a + PANEL * 2);
        }
    }

    float m0 = -1e30f, m1 = -1e30f, l0 = 0.0f, l1 = 0.0f;
    float o[8][4];
    #pragma unroll
    for (int t = 0; t < 8; t++)
        #pragma unroll
        for (int q = 0; q < 4; q++) o[t][q] = 0.0f;

    for (int j = 0; j < nkt; j++) {
        if (j > 0) {
            if (j + 1 < nkt) { CPW1; } else { CPW0; }
            __syncthreads();
        }
        const int st = j & 1;
        const uint32_t kb = smb + (uint32_t)(2 * PANEL + st * 4 * PANEL) * 2;

        float s[16][4];
        #pragma unroll
        for (int t = 0; t < 16; t++)
            #pragma unroll
            for (int q = 0; q < 4; q++) s[t][q] = 0.0f;

        #pragma unroll
        for (int kc = 0; kc < 4; kc++) {
            #pragma unroll
            for (int g = 0; g < 8; g++) {
                int rowb = g * 16 + (lane & 15);
                uint32_t ad = kb + (uint32_t)(rowb * STR + kc * 16 + ((lane >> 4) << 3)) * 2;
                uint32_t h0, h1, h2, h3, e0, e1, e2, e3;
                LDSM4(h0, h1, h2, h3, ad);
                LDSM4(e0, e1, e2, e3, ad + PANEL * 2);
                uint32_t bh0[2] = {h0, h2}, bh1[2] = {h1, h3};
                uint32_t bl0[2] = {e0, e2}, bl1[2] = {e1, e3};
                mma16816(s[2*g],     qH[kc], bh0);
                mma16816(s[2*g],     qH[kc], bl0);
                mma16816(s[2*g],     qL[kc], bh0);
                mma16816(s[2*g+1],   qH[kc], bh1);
                mma16816(s[2*g+1],   qH[kc], bl1);
                mma16816(s[2*g+1],   qL[kc], bh1);
            }
        }

        #pragma unroll
        for (int t = 0; t < 16; t++)
            #pragma unroll
            for (int q = 0; q < 4; q++) s[t][q] *= 0.125f;
        if ((j == nkt - 1) && (len & 127)) {
            #pragma unroll
            for (int t = 0; t < 16; t++) {
                int col = j * 128 + t * 8 + 2 * (lane & 3);
                if (col     >= len) { s[t][0] = -1e9f; s[t][2] = -1e9f; }
                if (col + 1 >= len) { s[t][1] = -1e9f; s[t][3] = -1e9f; }
            }
        }

        float mx0 = -1e30f, mx1 = -1e30f;
        #pragma unroll
        for (int t = 0; t < 16; t++) {
            mx0 = fmaxf(mx0, fmaxf(s[t][0], s[t][1]));
            mx1 = fmaxf(mx1, fmaxf(s[t][2], s[t][3]));
        }
        mx0 = fmaxf(mx0, __shfl_xor_sync(0xffffffffu, mx0, 1));
        mx0 = fmaxf(mx0, __shfl_xor_sync(0xffffffffu, mx0, 2));
        mx1 = fmaxf(mx1, __shfl_xor_sync(0xffffffffu, mx1, 1));
        mx1 = fmaxf(mx1, __shfl_xor_sync(0xffffffffu, mx1, 2));
        float mn0 = fmaxf(m0, mx0), mn1 = fmaxf(m1, mx1);
        float sc0 = __expf(m0 - mn0), sc1 = __expf(m1 - mn1);
        m0 = mn0; m1 = mn1;
        float sum0 = 0.0f, sum1 = 0.0f;
        #pragma unroll
        for (int t = 0; t < 16; t++) {
            s[t][0] = __expf(s[t][0] - mn0); sum0 += s[t][0];
            s[t][1] = __expf(s[t][1] - mn0); sum0 += s[t][1];
            s[t][2] = __expf(s[t][2] - mn1); sum1 += s[t][2];
            s[t][3] = __expf(s[t][3] - mn1); sum1 += s[t][3];
        }
        sum0 += __shfl_xor_sync(0xffffffffu, sum0, 1);
        sum0 += __shfl_xor_sync(0xffffffffu, sum0, 2);
        sum1 += __shfl_xor_sync(0xffffffffu, sum1, 1);
        sum1 += __shfl_xor_sync(0xffffffffu, sum1, 2);
        l0 = l0 * sc0 + sum0;
        l1 = l1 * sc1 + sum1;
        #pragma unroll
        for (int t = 0; t < 8; t++) {
            o[t][0] *= sc0; o[t][1] *= sc0;
            o[t][2] *= sc1; o[t][3] *= sc1;
        }

        #pragma unroll
        for (int kc = 0; kc < 8; kc++) {
            uint32_t pH[4], pL[4];
            {
                float a0 = s[2*kc][0],   a1 = s[2*kc][1];
                float a2 = s[2*kc][2],   a3 = s[2*kc][3];
                float b0 = s[2*kc+1][0], b1 = s[2*kc+1][1];
                float b2 = s[2*kc+1][2], b3 = s[2*kc+1][3];
                pH[0] = packbf(a0, a1); pH[1] = packbf(a2, a3);
                pH[2] = packbf(b0, b1); pH[3] = packbf(b2, b3);
                float ra0 = a0 - __bfloat162float(__float2bfloat16(a0));
                float ra1 = a1 - __bfloat162float(__float2bfloat16(a1));
                float ra2 = a2 - __bfloat162float(__float2bfloat16(a2));
                float ra3 = a3 - __bfloat162float(__float2bfloat16(a3));
                float rb0 = b0 - __bfloat162float(__float2bfloat16(b0));
                float rb1 = b1 - __bfloat162float(__float2bfloat16(b1));
                float rb2 = b2 - __bfloat162float(__float2bfloat16(b2));
                float rb3 = b3 - __bfloat162float(__float2bfloat16(b3));
                pL[0] = packbf(ra0, ra1); pL[1] = packbf(ra2, ra3);
                pL[2] = packbf(rb0, rb1); pL[3] = packbf(rb2, rb3);
            }
            #pragma unroll
            for (int g = 0; g < 4; g++) {
                int krow = kc * 16 + ((lane >> 3) & 1) * 8 + (lane & 7);
                int ncol = g * 16 + ((lane >> 4) << 3);
                uint32_t ad = kb + (uint32_t)(2 * PANEL + krow * STR + ncol) * 2;
                uint32_t h0, h1, h2, h3, e0, e1, e2, e3;
                LDSM4T(h0, h1, h2, h3, ad);
                LDSM4T(e0, e1, e2, e3, ad + PANEL * 2);
                uint32_t vh0[2] = {h0, h1}, vh1[2] = {h2, h3};
                uint32_t vl0[2] = {e0, e1}, vl1[2] = {e2, e3};
                mma16816(o[2*g],   pH, vh0);
                mma16816(o[2*g],   pH, vl0);
                mma16816(o[2*g],   pL, vh0);
                mma16816(o[2*g+1], pH, vh1);
                mma16816(o[2*g+1], pH, vl1);
                mma16816(o[2*g+1], pL, vh1);
            }
        }
        __syncthreads();
        if (j + 2 < nkt) load_kv(j + 2, st);
        CPC;
    }

    const int q0 = qt + wid * 16 + (lane >> 2);
    const int q1 = q0 + 8;
    const float inv0 = (q0 < len) ? (1.0f / l0) : 0.0f;
    const float inv1 = (q1 < len) ? (1.0f / l1) : 0.0f;
    const size_t b0 = (size_t)z * S_ * HD_ + (size_t)q0 * HD_;
    const size_t b1 = (size_t)z * S_ * HD_ + (size_t)q1 * HD_;
    #pragma unroll
    for (int t = 0; t < 8; t++) {
        int col = t * 8 + 2 * (lane & 3);
        float v0 = o[t][0] * inv0, v1 = o[t][1] * inv0;
        float v2 = o[t][2] * inv1, v3 = o[t][3] * inv1;
        float h0 = __bfloat162float(__float2bfloat16(v0));
        float h1 = __bfloat162float(__float2bfloat16(v1));
        float h2 = __bfloat162float(__float2bfloat16(v2));
        float h3 = __bfloat162float(__float2bfloat16(v3));
        *(uint32_t*)(ah + b0 + col) = packbf(v0, v1);
        *(uint32_t*)(al + b0 + col) = packbf(v0 - h0, v1 - h1);
        *(uint32_t*)(ah + b1 + col) = packbf(v2, v3);
        *(uint32_t*)(al + b1 + col) = packbf(v2 - h2, v3 - h3);
    }
}

// ===================== layernorm ============================================
__device__ __forceinline__ float warpSum(float v) {
    #pragma unroll
    for (int o = 16; o > 0; o >>= 1) v += __shfl_xor_sync(0xffffffffu, v, o);
    return v;
}

__global__ void add_ln(const float* __restrict__ Y, const float* __restrict__ R,
                       const float* __restrict__ g, const float* __restrict__ be,
                       float* __restrict__ outF, bf16* __restrict__ outH,
                       bf16* __restrict__ outL)
{
    const int r = blockIdx.x;
    const float* y = Y + (size_t)r * D_;
    const float* x = R + (size_t)r * D_;
    const int t = threadIdx.x;
    const int lane = t & 31, wid = t >> 5;
    __shared__ float sm1[4], sm2[4];
    float v[4], s = 0.0f;
    #pragma unroll
    for (int i = 0; i < 4; i++) { v[i] = y[t + 128*i] + x[t + 128*i]; s += v[i]; }
    float w = warpSum(s);
    if (lane == 0) sm1[wid] = w;
    __syncthreads();
    float mean = (sm1[0] + sm1[1] + sm1[2] + sm1[3]) * (1.0f / D_);
    float vs = 0.0f;
    #pragma unroll
    for (int i = 0; i < 4; i++) { float d = v[i] - mean; vs += d * d; }
    w = warpSum(vs);
    if (lane == 0) sm2[wid] = w;
    __syncthreads();
    float rstd = rsqrtf((sm2[0] + sm2[1] + sm2[2] + sm2[3]) * (1.0f / D_) + EPS_);
    #pragma unroll
    for (int i = 0; i < 4; i++) {
        int cc = t + 128 * i;
        float o = g[cc] * (v[i] - mean) * rstd + be[cc];
        size_t oi = (size_t)r * D_ + cc;
        outF[oi] = o;
        split_store(o, outH, outL, oi);
    }
}

// ===================== launch ===============================================
extern "C" void kernel_launch(void* const* d_in, const int* in_sizes, int n_in,
                              void* d_out, int out_size)
{
    const float* x    = (const float*)d_in[0];
    const unsigned char* mask = (const unsigned char*)d_in[1];
    const float* Wqkv = (const float*)d_in[2];
    const float* Wo   = (const float*)d_in[3];
    const float* bo   = (const float*)d_in[4];
    const float* g1   = (const float*)d_in[5];
    const float* be1  = (const float*)d_in[6];
    const float* W1   = (const float*)d_in[7];
    const float* bf1  = (const float*)d_in[8];
    const float* W2   = (const float*)d_in[9];
    const float* bf2  = (const float*)d_in[10];
    const float* g2   = (const float*)d_in[11];
    const float* be2  = (const float*)d_in[12];
    float* out = (float*)d_out;

    bf16 *xh, *xl, *qh, *ql, *ah, *al, *hh, *hl;
    float *Yf, *r1, *r2;
    bf16 *wqT[2], *woT[2], *w1T[2], *w2T[2];
    cudaGetSymbolAddress((void**)&xh, g_xh);   cudaGetSymbolAddress((void**)&xl, g_xl);
    cudaGetSymbolAddress((void**)&qh, g_qh);   cudaGetSymbolAddress((void**)&ql, g_ql);
    cudaGetSymbolAddress((void**)&ah, g_ah);   cudaGetSymbolAddress((void**)&al, g_al);
    cudaGetSymbolAddress((void**)&Yf, g_Yf);
    cudaGetSymbolAddress((void**)&r1, g_r1);   cudaGetSymbolAddress((void**)&r2, g_r2);
    cudaGetSymbolAddress((void**)&hh, g_hh);   cudaGetSymbolAddress((void**)&hl, g_hl);
    cudaGetSymbolAddress((void**)&wqT[0], g_wqT); cudaGetSymbolAddress((void**)&woT[0], g_woT);
    cudaGetSymbolAddress((void**)&w1T[0], g_w1T); cudaGetSymbolAddress((void**)&w2T[0], g_w2T);
    wqT[1] = wqT[0] + L_*3*D_*D_; woT[1] = woT[0] + L_*D_*D_;
    w1T[1] = w1T[0] + L_*FF_*D_;  w2T[1] = w2T[0] + L_*D_*FF_;

    const int SMB128 = 2 * (256 + 256) * 40 * 2;   // 81920 (2 stages, 2 CTAs/SM)
    const int SMFL   = 10 * 128 * 72 * 2;          // 184320
    cudaFuncSetAttribute(gemm_mma<128,0>, cudaFuncAttributeMaxDynamicSharedMemorySize, SMB128);
    cudaFuncSetAttribute(gemm_mma<128,2>, cudaFuncAttributeMaxDynamicSharedMemorySize, SMB128);
    cudaFuncSetAttribute(gemm_mma<128,3>, cudaFuncAttributeMaxDynamicSharedMemorySize, SMB128);
    cudaFuncSetAttribute(flash_attn,      cudaFuncAttributeMaxDynamicSharedMemorySize, SMFL);

    prep_mask<<<1, 256>>>(mask);
    convert_split<<<(B_*S_*D_ + 255)/256, 256>>>(x, xh, xl, B_*S_*D_);

    dim3 tb(32, 8);
    for (int l = 0; l < L_; l++) {
        transpose_split<<<dim3(3*D_/32, D_/32), tb>>>(Wqkv + (size_t)l*D_*3*D_,
            wqT[0] + (size_t)l*3*D_*D_, wqT[1] + (size_t)l*3*D_*D_, D_, 3*D_);
        transpose_split<<<dim3(D_/32, D_/32), tb>>>(Wo + (size_t)l*D_*D_,
            woT[0] + (size_t)l*D_*D_, woT[1] + (size_t)l*D_*D_, D_, D_);
        transpose_split<<<dim3(FF_/32, D_/32), tb>>>(W1 + (size_t)l*D_*FF_,
            w1T[0] + (size_t)l*FF_*D_, w1T[1] + (size_t)l*FF_*D_, D_, FF_);
        transpose_split<<<dim3(D_/32, FF_/32), tb>>>(W2 + (size_t)l*FF_*D_,
            w2T[0] + (size_t)l*D_*FF_, w2T[1] + (size_t)l*D_*FF_, FF_, D_);
    }

    const int M = B_ * S_;
    for (int l = 0; l < L_; l++) {
        const float* curF = (l == 0) ? x : r2;

        gemm_mma<128,2><<<dim3(3*D_/128, M/128, 1), 256, SMB128>>>(
            M, 3*D_, D_, xh, xl, D_, 0,
            wqT[0] + (size_t)l*3*D_*D_, wqT[1] + (size_t)l*3*D_*D_, D_, 0,
            nullptr, qh, ql, 3*D_, 0, nullptr);

        flash_attn<<<dim3(S_/128, B_*H_), 256, SMFL>>>(qh, ql, ah, al);

        gemm_mma<128,0><<<dim3(D_/128, M/128, 1), 256, SMB128>>>(
            M, D_, D_, ah, al, D_, 0,
            woT[0] + (size_t)l*D_*D_, woT[1] + (size_t)l*D_*D_, D_, 0,
            Yf, nullptr, nullptr, D_, 0, bo + (size_t)l*D_);

        add_ln<<<M, 128>>>(Yf, curF, g1 + (size_t)l*D_, be1 + (size_t)l*D_, r1, xh, xl);

        gemm_mma<128,3><<<dim3(FF_/128, M/128, 1), 256, SMB128>>>(
            M, FF_, D_, xh, xl, D_, 0,
            w1T[0] + (size_t)l*FF_*D_, w1T[1] + (size_t)l*FF_*D_, D_, 0,
            nullptr, hh, hl, FF_, 0, bf1 + (size_t)l*FF_);

        gemm_mma<128,0><<<dim3(D_/128, M/128, 1), 256, SMB128>>>(
            M, D_, FF_, hh, hl, FF_, 0,
            w2T[0] + (size_t)l*D_*FF_, w2T[1] + (size_t)l*D_*FF_, FF_, 0,
            Yf, nullptr, nullptr, D_, 0, bf2 + (size_t)l*D_);

        float* dst = (l == L_ - 1) ? out : r2;
        add_ln<<<M, 128>>>(Yf, r1, g2 + (size_t)l*D_, be2 + (size_t)l*D_, dst, xh, xl);
    }
    (void)in_sizes; (void)n_in; (void)out_size;
}

// round 9
// speedup vs baseline: 3.6641x; 1.0076x over previous
#include <cuda_runtime.h>
#include <cuda_bf16.h>
#include <cstdint>
#include <cstddef>

#define B_  2
#define S_  2048
#define D_  512
#define H_  8
#define HD_ 64
#define FF_ 2048
#define L_  2
#define EPS_ 1e-5f

typedef __nv_bfloat16 bf16;

// ===================== PTX helpers (non-'a' gated only) =====================
__device__ __forceinline__ uint32_t smem_u32(const void* p) {
    uint32_t a;
    asm("{ .reg .u64 t; cvta.to.shared.u64 t, %1; cvt.u32.u64 %0, t; }" : "=r"(a) : "l"(p));
    return a;
}
__device__ __forceinline__ void cp16(uint32_t dst, const void* src) {
    asm volatile("cp.async.cg.shared.global [%0], [%1], 16;" :: "r"(dst), "l"(src));
}
#define CPC  asm volatile("cp.async.commit_group;" ::: "memory")
#define CPW1 asm volatile("cp.async.wait_group 1;" ::: "memory")
#define CPW0 asm volatile("cp.async.wait_group 0;" ::: "memory")
#define LDSM4(r0, r1, r2, r3, a) \
    asm volatile("ldmatrix.sync.aligned.m8n8.x4.shared.b16 {%0,%1,%2,%3}, [%4];" \
                 : "=r"(r0), "=r"(r1), "=r"(r2), "=r"(r3) : "r"(a))
#define LDSM4T(r0, r1, r2, r3, a) \
    asm volatile("ldmatrix.sync.aligned.m8n8.x4.trans.shared.b16 {%0,%1,%2,%3}, [%4];" \
                 : "=r"(r0), "=r"(r1), "=r"(r2), "=r"(r3) : "r"(a))

__device__ __forceinline__ void mma16816(float* c, const uint32_t* a, const uint32_t* b) {
    asm volatile("mma.sync.aligned.m16n8k16.row.col.f32.bf16.bf16.f32 "
                 "{%0,%1,%2,%3}, {%4,%5,%6,%7}, {%8,%9}, {%0,%1,%2,%3};"
                 : "+f"(c[0]), "+f"(c[1]), "+f"(c[2]), "+f"(c[3])
                 : "r"(a[0]), "r"(a[1]), "r"(a[2]), "r"(a[3]), "r"(b[0]), "r"(b[1]));
}

__device__ __forceinline__ uint32_t packbf(float a, float b) {
    __nv_bfloat162 t = __floats2bfloat162_rn(a, b);
    return *(uint32_t*)&t;
}

// ===================== device scratch =======================================
__device__ int  g_len[B_];
__device__ bf16 g_xh[B_*S_*D_],  g_xl[B_*S_*D_];
__device__ bf16 g_qh[B_*S_*3*D_], g_ql[B_*S_*3*D_];
__device__ bf16 g_ah[B_*S_*D_], g_al[B_*S_*D_];
__device__ float g_Yf[B_*S_*D_], g_r1[B_*S_*D_], g_r2[B_*S_*D_];
__device__ bf16 g_hh[B_*S_*FF_], g_hl[B_*S_*FF_];
__device__ bf16 g_wqT[2][L_*3*D_*D_];
__device__ bf16 g_woT[2][L_*D_*D_];
__device__ bf16 g_w1T[2][L_*FF_*D_];
__device__ bf16 g_w2T[2][L_*D_*FF_];

__device__ __forceinline__ void split_store(float v, bf16* H, bf16* L, size_t i) {
    bf16 h = __float2bfloat16(v);
    H[i] = h;
    L[i] = __float2bfloat16(v - __bfloat162float(h));
}

// ===================== mask prep (validated R1) =============================
__global__ void prep_mask(const unsigned char* __restrict__ m8) {
    __shared__ int s_cnt, s_bad;
    const int* m32 = (const int*)m8;
    for (int b = 0; b < B_; b++) {
        if (threadIdx.x == 0) { s_cnt = 0; s_bad = 0; }
        __syncthreads();
        int local = 0;
        for (int j = threadIdx.x; j < S_; j += blockDim.x)
            local += (m8[b * S_ + j] != 0) ? 1 : 0;
        atomicAdd(&s_cnt, local);
        __syncthreads();
        int c = s_cnt, bad = 0;
        for (int j = threadIdx.x; j < S_; j += blockDim.x) {
            int v = (m8[b * S_ + j] != 0) ? 1 : 0;
            if (v != ((j < c) ? 1 : 0)) bad = 1;
        }
        if (bad) atomicOr(&s_bad, 1);
        __syncthreads();
        if (s_bad != 0 || c < S_ / 2) {
            if (threadIdx.x == 0) s_cnt = 0;
            __syncthreads();
            local = 0;
            for (int j = threadIdx.x; j < S_; j += blockDim.x)
                local += (m32[b * S_ + j] != 0) ? 1 : 0;
            atomicAdd(&s_cnt, local);
            __syncthreads();
            c = s_cnt;
        }
        if (threadIdx.x == 0) g_len[b] = c;
        __syncthreads();
    }
}

// ===================== conversions ==========================================
__global__ void convert_split(const float* __restrict__ in, bf16* __restrict__ hi,
                              bf16* __restrict__ lo, int n) {
    int i = blockIdx.x * blockDim.x + threadIdx.x;
    if (i < n) split_store(in[i], hi, lo, i);
}

// W[K,N] fp32 -> T[N,K] split bf16
__global__ void transpose_split(const float* __restrict__ W, bf16* __restrict__ Th,
                                bf16* __restrict__ Tl, int K, int N) {
    __shared__ float t[32][33];
    int n0 = blockIdx.x * 32, k0 = blockIdx.y * 32;
    int tx = threadIdx.x, ty = threadIdx.y;       // (32, 8)
    #pragma unroll
    for (int i = 0; i < 4; i++)
        t[ty + 8*i][tx] = W[(size_t)(k0 + ty + 8*i) * N + n0 + tx];
    __syncthreads();
    #pragma unroll
    for (int i = 0; i < 4; i++)
        split_store(t[tx][ty + 8*i], Th, Tl, (size_t)(n0 + ty + 8*i) * K + k0 + tx);
}

// ===================== mma.sync GEMM ========================================
// BM=64: 3-stage pipeline, 2 CTAs/SM.  BM=128: 2-stage, 2 CTAs/SM.
// EPI: 0 fp32 (+bias), 2 split-bf16 out, 3 bias+relu -> split-bf16 out
template<int BM, int EPI>
__global__ __launch_bounds__(256, 2)
void gemm_mma(int M, int N, int K,
              const bf16* __restrict__ Ah_, const bf16* __restrict__ Al_, int lda, size_t sA,
              const bf16* __restrict__ Bh_, const bf16* __restrict__ Bl_, int ldb, size_t sB,
              float* __restrict__ Cf, bf16* __restrict__ Ch, bf16* __restrict__ Cl,
              int ldc, size_t sC, const float* __restrict__ bias)
{
    constexpr int BN = 128;
    constexpr int STAGES = (BM == 64) ? 3 : 2;
    constexpr int WARPS_N = 4;                    // 8 warps = 2 x 4
    constexpr int WM = BM / 2;                    // 32 or 64
    constexpr int WN = 32;
    constexpr int MI = WM / 16;                   // 2 or 4
    constexpr int NI = WN / 8;                    // 4
    constexpr int STR = 40;                       // conflict-free 80B row stride
    constexpr int OFF_AL = BM * STR;
    constexpr int OFF_BH = 2 * BM * STR;
    constexpr int STG = (2 * BM + 2 * BN) * STR;  // elems per stage

    extern __shared__ __align__(16) bf16 sm[];

    const int z  = blockIdx.z;
    const int bm = blockIdx.y * BM;
    const int bn = blockIdx.x * BN;
    const int tid = threadIdx.x;
    const int wid = tid >> 5, lane = tid & 31;
    const int wm = wid / WARPS_N, wn = wid % WARPS_N;

    const int KP = K / 32;

    const bf16* pAh = Ah_ + (size_t)z * sA + (size_t)bm * lda;
    const bf16* pAl = Al_ + (size_t)z * sA + (size_t)bm * lda;
    const bf16* pBh = Bh_ + (size_t)z * sB + (size_t)bn * ldb;
    const bf16* pBl = Bl_ + (size_t)z * sB + (size_t)bn * ldb;
    const uint32_t smb = smem_u32(sm);

    auto load_stage = [&](int p, int st) {
        const size_t k0 = (size_t)p * 32;
        const uint32_t sb = smb + (uint32_t)st * STG * 2;
        for (int i = tid; i < BM * 4; i += 256) {
            int r = i >> 2, ch = i & 3;
            uint32_t d = sb + (uint32_t)(r * STR + ch * 8) * 2;
            cp16(d,               pAh + (size_t)r * lda + k0 + ch * 8);
            cp16(d + OFF_AL * 2,  pAl + (size_t)r * lda + k0 + ch * 8);
        }
        for (int i = tid; i < BN * 4; i += 256) {
            int r = i >> 2, ch = i & 3;
            uint32_t d = sb + (uint32_t)(OFF_BH + r * STR + ch * 8) * 2;
            cp16(d,                pBh + (size_t)r * ldb + k0 + ch * 8);
            cp16(d + BN * STR * 2, pBl + (size_t)r * ldb + k0 + ch * 8);
        }
    };

    float c[MI][NI][4];
    #pragma unroll
    for (int i = 0; i < MI; i++)
        #pragma unroll
        for (int j = 0; j < NI; j++)
            #pragma unroll
            for (int q = 0; q < 4; q++) c[i][j][q] = 0.0f;

    load_stage(0, 0); CPC;
    if (KP > 1) load_stage(1, 1);
    CPC;

    for (int p = 0; p < KP; p++) {
        if (p < KP - 1) { CPW1; } else { CPW0; }
        __syncthreads();
        const int st = p % STAGES;
        if (STAGES == 3) {
            if (p + 2 < KP) load_stage(p + 2, (p + 2) % 3);
            CPC;
        }
        const uint32_t sb = smb + (uint32_t)st * STG * 2;

        #pragma unroll
        for (int ks = 0; ks < 2; ks++) {
            const int colo = ks * 16 + (lane >> 4) * 8;
            uint32_t aH[MI][4], aL[MI][4], bH[NI][2], bL[NI][2];
            #pragma unroll
            for (int mi = 0; mi < MI; mi++) {
                int row = wm * WM + mi * 16 + (lane & 15);
                uint32_t ad = sb + (uint32_t)(row * STR + colo) * 2;
                LDSM4(aH[mi][0], aH[mi][1], aH[mi][2], aH[mi][3], ad);
                LDSM4(aL[mi][0], aL[mi][1], aL[mi][2], aL[mi][3], ad + OFF_AL * 2);
            }
            #pragma unroll
            for (int j2 = 0; j2 < NI / 2; j2++) {
                int rowb = wn * WN + j2 * 16 + (lane & 15);
                uint32_t bd = sb + (uint32_t)(OFF_BH + rowb * STR + colo) * 2;
                uint32_t r0, r1, r2, r3;
                LDSM4(r0, r1, r2, r3, bd);
                bH[2*j2][0] = r0; bH[2*j2][1] = r2;
                bH[2*j2+1][0] = r1; bH[2*j2+1][1] = r3;
                LDSM4(r0, r1, r2, r3, bd + BN * STR * 2);
                bL[2*j2][0] = r0; bL[2*j2][1] = r2;
                bL[2*j2+1][0] = r1; bL[2*j2+1][1] = r3;
            }
            #pragma unroll
            for (int mi = 0; mi < MI; mi++)
                #pragma unroll
                for (int nj = 0; nj < NI; nj++) {
                    mma16816(c[mi][nj], aH[mi], bH[nj]);
                    mma16816(c[mi][nj], aH[mi], bL[nj]);
                    mma16816(c[mi][nj], aL[mi], bH[nj]);
                }
        }
        if (STAGES == 2) {
            __syncthreads();
            if (p + 2 < KP) load_stage(p + 2, st);
            CPC;
        }
    }

    #pragma unroll
    for (int mi = 0; mi < MI; mi++) {
        const int row = bm + wm * WM + mi * 16 + (lane >> 2);
        #pragma unroll
        for (int nj = 0; nj < NI; nj++) {
            const int col = bn + wn * WN + nj * 8 + 2 * (lane & 3);
            const size_t i0 = (size_t)z * sC + (size_t)row * ldc + col;
            const size_t i1 = i0 + (size_t)8 * ldc;
            float v0 = c[mi][nj][0], v1 = c[mi][nj][1];
            float v2 = c[mi][nj][2], v3 = c[mi][nj][3];
            if (EPI == 0) {
                if (bias) { v0 += bias[col]; v1 += bias[col + 1]; v2 += bias[col]; v3 += bias[col + 1]; }
                *(float2*)(Cf + i0) = make_float2(v0, v1);
                *(float2*)(Cf + i1) = make_float2(v2, v3);
            } else {
                if (EPI == 3) {
                    v0 = fmaxf(v0 + bias[col], 0.0f); v1 = fmaxf(v1 + bias[col + 1], 0.0f);
                    v2 = fmaxf(v2 + bias[col], 0.0f); v3 = fmaxf(v3 + bias[col + 1], 0.0f);
                }
                float h0 = __bfloat162float(__float2bfloat16(v0));
                float h1 = __bfloat162float(__float2bfloat16(v1));
                float h2 = __bfloat162float(__float2bfloat16(v2));
                float h3 = __bfloat162float(__float2bfloat16(v3));
                *(uint32_t*)(Ch + i0) = packbf(v0, v1);
                *(uint32_t*)(Cl + i0) = packbf(v0 - h0, v1 - h1);
                *(uint32_t*)(Ch + i1) = packbf(v2, v3);
                *(uint32_t*)(Cl + i1) = packbf(v2 - h2, v3 - h3);
            }
        }
    }
}

// ===================== fused flash attention ================================
__global__ __launch_bounds__(256, 1)
void flash_attn(const bf16* __restrict__ qh, const bf16* __restrict__ ql,
                bf16* __restrict__ ah, bf16* __restrict__ al)
{
    constexpr int STR = 72;
    constexpr int PANEL = 128 * STR;
    extern __shared__ __align__(16) bf16 sm[];

    const int z   = blockIdx.y;
    const int qt  = blockIdx.x * 128;
    const int len = g_len[z / H_];
    const int tid = threadIdx.x, wid = tid >> 5, lane = tid & 31;

    if (qt >= len) {
        uint4 zz = make_uint4(0, 0, 0, 0);
        const size_t ob = (size_t)z * S_ * HD_ + (size_t)qt * HD_;
        for (int i = tid; i < 128 * HD_ / 8; i += 256) {
            *(uint4*)(ah + ob + (size_t)i * 8) = zz;
            *(uint4*)(al + ob + (size_t)i * 8) = zz;
        }
        return;
    }

    const int nkt = (len + 127) >> 7;
    const uint32_t smb = smem_u32(sm);
    const size_t hbase = (size_t)z * S_ * 192;

    for (int i = tid; i < 128 * 8; i += 256) {
        int r = i >> 3, ch = i & 7;
        uint32_t d = smb + (uint32_t)(r * STR + ch * 8) * 2;
        const size_t g = hbase + (size_t)(qt + r) * 192 + ch * 8;
        cp16(d, qh + g);
        cp16(d + PANEL * 2, ql + g);
    }
    auto load_kv = [&](int j, int st) {
        const uint32_t sb = smb + (uint32_t)(2 * PANEL + st * 4 * PANEL) * 2;
        for (int i = tid; i < 128 * 8; i += 256) {
            int r = i >> 3, ch = i & 7;
            uint32_t d = sb + (uint32_t)(r * STR + ch * 8) * 2;
            const size_t g = hbase + (size_t)(j * 128 + r) * 192 + ch * 8;
            cp16(d,                 qh + g + 64);
            cp16(d + PANEL * 2,     ql + g + 64);
            cp16(d + 2 * PANEL * 2, qh + g + 128);
            cp16(d + 3 * PANEL * 2, ql + g + 128);
        }
    };
    load_kv(0, 0); CPC;
    if (nkt > 1) load_kv(1, 1);
    CPC;
    CPW1; __syncthreads();

    uint32_t qH[4][4], qL[4][4];
    {
        int row = wid * 16 + (lane & 15);
        #pragma unroll
        for (int kc = 0; kc < 4; kc++) {
            uint32_t a = smb + (uint32_t)(row * STR + kc * 16 + ((lane >> 4) << 3)) * 2;
            LDSM4(qH[kc][0], qH[kc][1], qH[kc][2], qH[kc][3], a);
            LDSM4(qL[kc][0], qL[kc][1], qL[kc][2], qL[kc][3], a + PANEL * 2);
        }
    }

    float m0 = -1e30f, m1 = -1e30f, l0 = 0.0f, l1 = 0.0f;
    float o[8][4];
    #pragma unroll
    for (int t = 0; t < 8; t++)
        #pragma unroll
        for (int q = 0; q < 4; q++) o[t][q] = 0.0f;

    for (int j = 0; j < nkt; j++) {
        if (j > 0) {
            if (j + 1 < nkt) { CPW1; } else { CPW0; }
            __syncthreads();
        }
        const int st = j & 1;
        const uint32_t kb = smb + (uint32_t)(2 * PANEL + st * 4 * PANEL) * 2;

        float s[16][4];
        #pragma unroll
        for (int t = 0; t < 16; t++)
            #pragma unroll
            for (int q = 0; q < 4; q++) s[t][q] = 0.0f;

        #pragma unroll
        for (int kc = 0; kc < 4; kc++) {
            #pragma unroll
            for (int g = 0; g < 8; g++) {
                int rowb = g * 16 + (lane & 15);
                uint32_t ad = kb + (uint32_t)(rowb * STR + kc * 16 + ((lane >> 4) << 3)) * 2;
                uint32_t h0, h1, h2, h3, e0, e1, e2, e3;
                LDSM4(h0, h1, h2, h3, ad);
                LDSM4(e0, e1, e2, e3, ad + PANEL * 2);
                uint32_t bh0[2] = {h0, h2}, bh1[2] = {h1, h3};
                uint32_t bl0[2] = {e0, e2}, bl1[2] = {e1, e3};
                mma16816(s[2*g],     qH[kc], bh0);
                mma16816(s[2*g],     qH[kc], bl0);
                mma16816(s[2*g],     qL[kc], bh0);
                mma16816(s[2*g+1],   qH[kc], bh1);
                mma16816(s[2*g+1],   qH[kc], bl1);
                mma16816(s[2*g+1],   qL[kc], bh1);
            }
        }

        #pragma unroll
        for (int t = 0; t < 16; t++)
            #pragma unroll
            for (int q = 0; q < 4; q++) s[t][q] *= 0.125f;
        if ((j == nkt - 1) && (len & 127)) {
            #pragma unroll
            for (int t = 0; t < 16; t++) {
                int col = j * 128 + t * 8 + 2 * (lane & 3);
                if (col     >= len) { s[t][0] = -1e9f; s[t][2] = -1e9f; }
                if (col + 1 >= len) { s[t][1] = -1e9f; s[t][3] = -1e9f; }
            }
        }

        float mx0 = -1e30f, mx1 = -1e30f;
        #pragma unroll
        for (int t = 0; t < 16; t++) {
            mx0 = fmaxf(mx0, fmaxf(s[t][0], s[t][1]));
            mx1 = fmaxf(mx1, fmaxf(s[t][2], s[t][3]));
        }
        mx0 = fmaxf(mx0, __shfl_xor_sync(0xffffffffu, mx0, 1));
        mx0 = fmaxf(mx0, __shfl_xor_sync(0xffffffffu, mx0, 2));
        mx1 = fmaxf(mx1, __shfl_xor_sync(0xffffffffu, mx1, 1));
        mx1 = fmaxf(mx1, __shfl_xor_sync(0xffffffffu, mx1, 2));
        float mn0 = fmaxf(m0, mx0), mn1 = fmaxf(m1, mx1);
        float sc0 = __expf(m0 - mn0), sc1 = __expf(m1 - mn1);
        m0 = mn0; m1 = mn1;
        float sum0 = 0.0f, sum1 = 0.0f;
        #pragma unroll
        for (int t = 0; t < 16; t++) {
            s[t][0] = __expf(s[t][0] - mn0); sum0 += s[t][0];
            s[t][1] = __expf(s[t][1] - mn0); sum0 += s[t][1];
            s[t][2] = __expf(s[t][2] - mn1); sum1 += s[t][2];
            s[t][3] = __expf(s[t][3] - mn1); sum1 += s[t][3];
        }
        sum0 += __shfl_xor_sync(0xffffffffu, sum0, 1);
        sum0 += __shfl_xor_sync(0xffffffffu, sum0, 2);
        sum1 += __shfl_xor_sync(0xffffffffu, sum1, 1);
        sum1 += __shfl_xor_sync(0xffffffffu, sum1, 2);
        l0 = l0 * sc0 + sum0;
        l1 = l1 * sc1 + sum1;
        #pragma unroll
        for (int t = 0; t < 8; t++) {
            o[t][0] *= sc0; o[t][1] *= sc0;
            o[t][2] *= sc1; o[t][3] *= sc1;
        }

        #pragma unroll
        for (int kc = 0; kc < 8; kc++) {
            uint32_t pH[4], pL[4];
            {
                float a0 = s[2*kc][0],   a1 = s[2*kc][1];
                float a2 = s[2*kc][2],   a3 = s[2*kc][3];
                float b0 = s[2*kc+1][0], b1 = s[2*kc+1][1];
                float b2 = s[2*kc+1][2], b3 = s[2*kc+1][3];
                pH[0] = packbf(a0, a1); pH[1] = packbf(a2, a3);
                pH[2] = packbf(b0, b1); pH[3] = packbf(b2, b3);
                float ra0 = a0 - __bfloat162float(__float2bfloat16(a0));
                float ra1 = a1 - __bfloat162float(__float2bfloat16(a1));
                float ra2 = a2 - __bfloat162float(__float2bfloat16(a2));
                float ra3 = a3 - __bfloat162float(__float2bfloat16(a3));
                float rb0 = b0 - __bfloat162float(__float2bfloat16(b0));
                float rb1 = b1 - __bfloat162float(__float2bfloat16(b1));
                float rb2 = b2 - __bfloat162float(__float2bfloat16(b2));
                float rb3 = b3 - __bfloat162float(__float2bfloat16(b3));
                pL[0] = packbf(ra0, ra1); pL[1] = packbf(ra2, ra3);
                pL[2] = packbf(rb0, rb1); pL[3] = packbf(rb2, rb3);
            }
            #pragma unroll
            for (int g = 0; g < 4; g++) {
                int krow = kc * 16 + ((lane >> 3) & 1) * 8 + (lane & 7);
                int ncol = g * 16 + ((lane >> 4) << 3);
                uint32_t ad = kb + (uint32_t)(2 * PANEL + krow * STR + ncol) * 2;
                uint32_t h0, h1, h2, h3, e0, e1, e2, e3;
                LDSM4T(h0, h1, h2, h3, ad);
                LDSM4T(e0, e1, e2, e3, ad + PANEL * 2);
                uint32_t vh0[2] = {h0, h1}, vh1[2] = {h2, h3};
                uint32_t vl0[2] = {e0, e1}, vl1[2] = {e2, e3};
                mma16816(o[2*g],   pH, vh0);
                mma16816(o[2*g],   pH, vl0);
                mma16816(o[2*g],   pL, vh0);
                mma16816(o[2*g+1], pH, vh1);
                mma16816(o[2*g+1], pH, vl1);
                mma16816(o[2*g+1], pL, vh1);
            }
        }
        __syncthreads();
        if (j + 2 < nkt) load_kv(j + 2, st);
        CPC;
    }

    const int q0 = qt + wid * 16 + (lane >> 2);
    const int q1 = q0 + 8;
    const float inv0 = (q0 < len) ? (1.0f / l0) : 0.0f;
    const float inv1 = (q1 < len) ? (1.0f / l1) : 0.0f;
    const size_t b0 = (size_t)z * S_ * HD_ + (size_t)q0 * HD_;
    const size_t b1 = (size_t)z * S_ * HD_ + (size_t)q1 * HD_;
    #pragma unroll
    for (int t = 0; t < 8; t++) {
        int col = t * 8 + 2 * (lane & 3);
        float v0 = o[t][0] * inv0, v1 = o[t][1] * inv0;
        float v2 = o[t][2] * inv1, v3 = o[t][3] * inv1;
        float h0 = __bfloat162float(__float2bfloat16(v0));
        float h1 = __bfloat162float(__float2bfloat16(v1));
        float h2 = __bfloat162float(__float2bfloat16(v2));
        float h3 = __bfloat162float(__float2bfloat16(v3));
        *(uint32_t*)(ah + b0 + col) = packbf(v0, v1);
        *(uint32_t*)(al + b0 + col) = packbf(v0 - h0, v1 - h1);
        *(uint32_t*)(ah + b1 + col) = packbf(v2, v3);
        *(uint32_t*)(al + b1 + col) = packbf(v2 - h2, v3 - h3);
    }
}

// ===================== layernorm ============================================
__device__ __forceinline__ float warpSum(float v) {
    #pragma unroll
    for (int o = 16; o > 0; o >>= 1) v += __shfl_xor_sync(0xffffffffu, v, o);
    return v;
}

__global__ void add_ln(const float* __restrict__ Y, const float* __restrict__ R,
                       const float* __restrict__ g, const float* __restrict__ be,
                       float* __restrict__ outF, bf16* __restrict__ outH,
                       bf16* __restrict__ outL)
{
    const int r = blockIdx.x;
    const float* y = Y + (size_t)r * D_;
    const float* x = R + (size_t)r * D_;
    const int t = threadIdx.x;
    const int lane = t & 31, wid = t >> 5;
    __shared__ float sm1[4], sm2[4];
    float v[4], s = 0.0f;
    #pragma unroll
    for (int i = 0; i < 4; i++) { v[i] = y[t + 128*i] + x[t + 128*i]; s += v[i]; }
    float w = warpSum(s);
    if (lane == 0) sm1[wid] = w;
    __syncthreads();
    float mean = (sm1[0] + sm1[1] + sm1[2] + sm1[3]) * (1.0f / D_);
    float vs = 0.0f;
    #pragma unroll
    for (int i = 0; i < 4; i++) { float d = v[i] - mean; vs += d * d; }
    w = warpSum(vs);
    if (lane == 0) sm2[wid] = w;
    __syncthreads();
    float rstd = rsqrtf((sm2[0] + sm2[1] + sm2[2] + sm2[3]) * (1.0f / D_) + EPS_);
    #pragma unroll
    for (int i = 0; i < 4; i++) {
        int cc = t + 128 * i;
        float o = g[cc] * (v[i] - mean) * rstd + be[cc];
        size_t oi = (size_t)r * D_ + cc;
        outF[oi] = o;
        split_store(o, outH, outL, oi);
    }
}

// ===================== launch ===============================================
extern "C" void kernel_launch(void* const* d_in, const int* in_sizes, int n_in,
                              void* d_out, int out_size)
{
    const float* x    = (const float*)d_in[0];
    const unsigned char* mask = (const unsigned char*)d_in[1];
    const float* Wqkv = (const float*)d_in[2];
    const float* Wo   = (const float*)d_in[3];
    const float* bo   = (const float*)d_in[4];
    const float* g1   = (const float*)d_in[5];
    const float* be1  = (const float*)d_in[6];
    const float* W1   = (const float*)d_in[7];
    const float* bf1  = (const float*)d_in[8];
    const float* W2   = (const float*)d_in[9];
    const float* bf2  = (const float*)d_in[10];
    const float* g2   = (const float*)d_in[11];
    const float* be2  = (const float*)d_in[12];
    float* out = (float*)d_out;

    bf16 *xh, *xl, *qh, *ql, *ah, *al, *hh, *hl;
    float *Yf, *r1, *r2;
    bf16 *wqT[2], *woT[2], *w1T[2], *w2T[2];
    cudaGetSymbolAddress((void**)&xh, g_xh);   cudaGetSymbolAddress((void**)&xl, g_xl);
    cudaGetSymbolAddress((void**)&qh, g_qh);   cudaGetSymbolAddress((void**)&ql, g_ql);
    cudaGetSymbolAddress((void**)&ah, g_ah);   cudaGetSymbolAddress((void**)&al, g_al);
    cudaGetSymbolAddress((void**)&Yf, g_Yf);
    cudaGetSymbolAddress((void**)&r1, g_r1);   cudaGetSymbolAddress((void**)&r2, g_r2);
    cudaGetSymbolAddress((void**)&hh, g_hh);   cudaGetSymbolAddress((void**)&hl, g_hl);
    cudaGetSymbolAddress((void**)&wqT[0], g_wqT); cudaGetSymbolAddress((void**)&woT[0], g_woT);
    cudaGetSymbolAddress((void**)&w1T[0], g_w1T); cudaGetSymbolAddress((void**)&w2T[0], g_w2T);
    wqT[1] = wqT[0] + L_*3*D_*D_; woT[1] = woT[0] + L_*D_*D_;
    w1T[1] = w1T[0] + L_*FF_*D_;  w2T[1] = w2T[0] + L_*D_*FF_;

    const int SMB64  = 3 * (128 + 256) * 40 * 2;   // 92160 (3 stages, BM=64)
    const int SMB128 = 2 * (256 + 256) * 40 * 2;   // 81920 (2 stages, BM=128)
    const int SMFL   = 10 * 128 * 72 * 2;          // 184320
    cudaFuncSetAttribute(gemm_mma<64,0>,  cudaFuncAttributeMaxDynamicSharedMemorySize, SMB64);
    cudaFuncSetAttribute(gemm_mma<64,2>,  cudaFuncAttributeMaxDynamicSharedMemorySize, SMB64);
    cudaFuncSetAttribute(gemm_mma<128,3>, cudaFuncAttributeMaxDynamicSharedMemorySize, SMB128);
    cudaFuncSetAttribute(flash_attn,      cudaFuncAttributeMaxDynamicSharedMemorySize, SMFL);

    prep_mask<<<1, 256>>>(mask);
    convert_split<<<(B_*S_*D_ + 255)/256, 256>>>(x, xh, xl, B_*S_*D_);

    dim3 tb(32, 8);
    for (int l = 0; l < L_; l++) {
        transpose_split<<<dim3(3*D_/32, D_/32), tb>>>(Wqkv + (size_t)l*D_*3*D_,
            wqT[0] + (size_t)l*3*D_*D_, wqT[1] + (size_t)l*3*D_*D_, D_, 3*D_);
        transpose_split<<<dim3(D_/32, D_/32), tb>>>(Wo + (size_t)l*D_*D_,
            woT[0] + (size_t)l*D_*D_, woT[1] + (size_t)l*D_*D_, D_, D_);
        transpose_split<<<dim3(FF_/32, D_/32), tb>>>(W1 + (size_t)l*D_*FF_,
            w1T[0] + (size_t)l*FF_*D_, w1T[1] + (size_t)l*FF_*D_, D_, FF_);
        transpose_split<<<dim3(D_/32, FF_/32), tb>>>(W2 + (size_t)l*FF_*D_,
            w2T[0] + (size_t)l*D_*FF_, w2T[1] + (size_t)l*D_*FF_, FF_, D_);
    }

    const int M = B_ * S_;
    for (int l = 0; l < L_; l++) {
        const float* curF = (l == 0) ? x : r2;

        // QKV: BM=64, grid 12x64 = 768 CTAs
        gemm_mma<64,2><<<dim3(3*D_/128, M/64, 1), 256, SMB64>>>(
            M, 3*D_, D_, xh, xl, D_, 0,
            wqT[0] + (size_t)l*3*D_*D_, wqT[1] + (size_t)l*3*D_*D_, D_, 0,
            nullptr, qh, ql, 3*D_, 0, nullptr);

        flash_attn<<<dim3(S_/128, B_*H_), 256, SMFL>>>(qh, ql, ah, al);

        // Wo: BM=64, grid 4x64 = 256 CTAs (one full wave @ 2 CTAs/SM)
        gemm_mma<64,0><<<dim3(D_/128, M/64, 1), 256, SMB64>>>(
            M, D_, D_, ah, al, D_, 0,
            woT[0] + (size_t)l*D_*D_, woT[1] + (size_t)l*D_*D_, D_, 0,
            Yf, nullptr, nullptr, D_, 0, bo + (size_t)l*D_);

        add_ln<<<M, 128>>>(Yf, curF, g1 + (size_t)l*D_, be1 + (size_t)l*D_, r1, xh, xl);

        // FFN1: BM=128, grid 16x32 = 512 CTAs
        gemm_mma<128,3><<<dim3(FF_/128, M/128, 1), 256, SMB128>>>(
            M, FF_, D_, xh, xl, D_, 0,
            w1T[0] + (size_t)l*FF_*D_, w1T[1] + (size_t)l*FF_*D_, D_, 0,
            nullptr, hh, hl, FF_, 0, bf1 + (size_t)l*FF_);

        // FFN2: BM=64, grid 4x64 = 256 CTAs, K=2048
        gemm_mma<64,0><<<dim3(D_/128, M/64, 1), 256, SMB64>>>(
            M, D_, FF_, hh, hl, FF_, 0,
            w2T[0] + (size_t)l*D_*FF_, w2T[1] + (size_t)l*D_*FF_, FF_, 0,
            Yf, nullptr, nullptr, D_, 0, bf2 + (size_t)l*D_);

        float* dst = (l == L_ - 1) ? out : r2;
        add_ln<<<M, 128>>>(Yf, r1, g2 + (size_t)l*D_, be2 + (size_t)l*D_, dst, xh, xl);
    }
    (void)in_sizes; (void)n_in; (void)out_size;
}